// round 4
// baseline (speedup 1.0000x reference)
#include <cuda_runtime.h>
#include <cuda_bf16.h>
#include <math.h>
#include <stdint.h>

// ---------------- problem constants ----------------
#define NN      50000
#define NPREV   50000
#define NFEATS  256
#define NHID    256
#define NHEADS  4
#define HD      64
#define DEG_IN  16
#define DEG_C   8
#define ALPHA   0.2f

// ---------------- device scratch ----------------
__device__ float d_Wh  [NN * NHID];
__device__ float d_x   [NN * NHID];
__device__ float d_Whp [NPREV * NHID];
__device__ float d_h   [NN * NHID];
__device__ float d_gi  [NN * 3 * NHID];
__device__ float d_gh  [NN * 3 * NHID];
__device__ float d_pk_intra[NHID * NFEATS];   // [n][k] row-major
__device__ float d_pk_cross[NHID * NHID];
__device__ float d_vmat[NFEATS * NHEADS];     // v[f][h] = sum_d Wc[h][f][d]*a2[h][d]
__device__ float d_es [NN * NHEADS];
__device__ float d_ed [NN * NHEADS];
__device__ float d_esP[NPREV * NHEADS];
__device__ float d_edX[NN * NHEADS];

// ---------------- helpers ----------------
__device__ __forceinline__ uint32_t f2tf32(float x) {
    uint32_t r;
    asm("cvt.rna.tf32.f32 %0, %1;" : "=r"(r) : "f"(x));
    return r;
}
__device__ __forceinline__ void mma_tf32(float* d, const uint32_t* a, const uint32_t* b) {
    asm volatile(
        "mma.sync.aligned.m16n8k8.row.col.f32.tf32.tf32.f32 "
        "{%0,%1,%2,%3},{%4,%5,%6,%7},{%8,%9},{%0,%1,%2,%3};"
        : "+f"(d[0]), "+f"(d[1]), "+f"(d[2]), "+f"(d[3])
        : "r"(a[0]), "r"(a[1]), "r"(a[2]), "r"(a[3]), "r"(b[0]), "r"(b[1]));
}

// ---------------- mma.sync tf32 GEMM, fragment-layout staged ----------------
// C[M, Nld] cols [n0,n0+128) = A[M,256] @ B[n][k]^T + bias
// SPLIT=1: A split tf32 hi+lo (fp32-accurate). DOTS: 0 none, 1 es+ed, 2 es.
// SMEM planes (u32): Ahi[4096] | B[4096] | Alo[4096 if SPLIT]
#define BMM 128
#define PLANE 16384
#define SMEM_SPLIT 49152
#define SMEM_PLAIN 32768

template<int DOTS, int SPLIT>
__global__ void __launch_bounds__(256, 2)
gemm_mma(const float* __restrict__ A, const float* __restrict__ B,
         const float* __restrict__ bias, const float* __restrict__ avec,
         float* __restrict__ C, float* __restrict__ es, float* __restrict__ ed,
         int M, int Nld) {
    extern __shared__ char smem[];
    uint32_t* sAhi = (uint32_t*)smem;
    uint32_t* sB   = (uint32_t*)(smem + PLANE);
    uint32_t* sAlo = (uint32_t*)(smem + 2 * PLANE);

    const int tid = threadIdx.x;
    const int wid = tid >> 5, lane = tid & 31;
    const int wm = wid & 3, wn = wid >> 2;     // warp tile 32(M) x 64(N)
    const int g = lane >> 2, t = lane & 3;
    const int m0 = blockIdx.x * BMM;
    const int n0 = blockIdx.y * BMM;

    const int rb = tid >> 3;    // staging base row (j*32 added)
    const int c4 = tid & 7;     // 16B chunk within 32-float K slab

    float acc[2][8][4];
    #pragma unroll
    for (int ma = 0; ma < 2; ma++)
        #pragma unroll
        for (int na = 0; na < 8; na++)
            #pragma unroll
            for (int q = 0; q < 4; q++) acc[ma][na][q] = 0.f;

    float4 pa[4], pb[4];
    // prologue: load chunk 0
    #pragma unroll
    for (int j = 0; j < 4; j++) {
        int r = rb + j * 32;
        int row = m0 + r; if (row >= M) row = M - 1;
        pa[j] = *(const float4*)&A[(size_t)row * 256 + c4 * 4];
        pb[j] = *(const float4*)&B[(size_t)(n0 + r) * 256 + c4 * 4];
    }

    for (int cc = 0; cc < 8; cc++) {
        if (cc > 0) __syncthreads();
        // ---- store staged regs in fragment layout (convert once) ----
        #pragma unroll
        for (int j = 0; j < 4; j++) {
            int r = rb + j * 32;
            int mt = r >> 4, kc = c4 >> 1;
            int regA = ((c4 & 1) << 1) | ((r >> 3) & 1);
            uint32_t abase = (uint32_t)(((mt * 4 + kc) * 32 + (r & 7) * 4) * 4 + regA);
            float av[4] = {pa[j].x, pa[j].y, pa[j].z, pa[j].w};
            #pragma unroll
            for (int q = 0; q < 4; q++) {
                uint32_t hi = f2tf32(av[q]);
                sAhi[abase + q * 4] = hi;
                if (SPLIT) sAlo[abase + q * 4] = f2tf32(av[q] - __uint_as_float(hi));
            }
            int nt = r >> 3;
            uint32_t bbase = (uint32_t)(((nt * 4 + kc) * 32 + (r & 7) * 4) * 2 + (c4 & 1));
            float bv[4] = {pb[j].x, pb[j].y, pb[j].z, pb[j].w};
            #pragma unroll
            for (int q = 0; q < 4; q++)
                sB[bbase + q * 2] = f2tf32(bv[q]);
        }
        __syncthreads();
        // ---- prefetch next chunk ----
        if (cc < 7) {
            #pragma unroll
            for (int j = 0; j < 4; j++) {
                int r = rb + j * 32;
                int row = m0 + r; if (row >= M) row = M - 1;
                pa[j] = *(const float4*)&A[(size_t)row * 256 + (cc + 1) * 32 + c4 * 4];
                pb[j] = *(const float4*)&B[(size_t)(n0 + r) * 256 + (cc + 1) * 32 + c4 * 4];
            }
        }
        // ---- compute: pure LDS + HMMA ----
        #pragma unroll
        for (int ks = 0; ks < 4; ks++) {
            uint4 aHi[2], aLo[2];
            #pragma unroll
            for (int ma = 0; ma < 2; ma++) {
                int mt = wm * 2 + ma;
                aHi[ma] = *(const uint4*)&sAhi[((mt * 4 + ks) * 32 + lane) * 4];
                if (SPLIT)
                    aLo[ma] = *(const uint4*)&sAlo[((mt * 4 + ks) * 32 + lane) * 4];
            }
            #pragma unroll
            for (int na = 0; na < 8; na++) {
                int nt = wn * 8 + na;
                uint2 bb = *(const uint2*)&sB[((nt * 4 + ks) * 32 + lane) * 2];
                #pragma unroll
                for (int ma = 0; ma < 2; ma++) {
                    mma_tf32(acc[ma][na], &aHi[ma].x, &bb.x);
                    if (SPLIT) mma_tf32(acc[ma][na], &aLo[ma].x, &bb.x);
                }
            }
        }
    }

    // ---- epilogue ----
    if (bias != nullptr) {
        #pragma unroll
        for (int na = 0; na < 8; na++)
            #pragma unroll
            for (int j = 0; j < 2; j++) {
                float bv = __ldg(&bias[n0 + wn * 64 + na * 8 + 2 * t + j]);
                acc[0][na][j]     += bv;
                acc[0][na][2 + j] += bv;
                acc[1][na][j]     += bv;
                acc[1][na][2 + j] += bv;
            }
    }

    int rbase = m0 + wm * 32;

    if (DOTS != 0) {
        int h = blockIdx.y * 2 + wn;
        float e1[4] = {0.f, 0.f, 0.f, 0.f};
        float e2[4] = {0.f, 0.f, 0.f, 0.f};
        #pragma unroll
        for (int na = 0; na < 8; na++)
            #pragma unroll
            for (int j = 0; j < 2; j++) {
                int cw = na * 8 + 2 * t + j;
                float a1 = __ldg(&avec[h * 128 + cw]);
                float a2 = __ldg(&avec[h * 128 + 64 + cw]);
                e1[0] = fmaf(acc[0][na][j], a1, e1[0]);
                e1[1] = fmaf(acc[0][na][2 + j], a1, e1[1]);
                e1[2] = fmaf(acc[1][na][j], a1, e1[2]);
                e1[3] = fmaf(acc[1][na][2 + j], a1, e1[3]);
                e2[0] = fmaf(acc[0][na][j], a2, e2[0]);
                e2[1] = fmaf(acc[0][na][2 + j], a2, e2[1]);
                e2[2] = fmaf(acc[1][na][j], a2, e2[2]);
                e2[3] = fmaf(acc[1][na][2 + j], a2, e2[3]);
            }
        #pragma unroll
        for (int s = 0; s < 4; s++) {
            e1[s] += __shfl_xor_sync(0xffffffffu, e1[s], 1);
            e1[s] += __shfl_xor_sync(0xffffffffu, e1[s], 2);
            e2[s] += __shfl_xor_sync(0xffffffffu, e2[s], 1);
            e2[s] += __shfl_xor_sync(0xffffffffu, e2[s], 2);
        }
        if (t == 0) {
            int rows[4] = {rbase + g, rbase + 8 + g, rbase + 16 + g, rbase + 24 + g};
            #pragma unroll
            for (int s = 0; s < 4; s++) {
                if (rows[s] < M) {
                    es[rows[s] * 4 + h] = e1[s];
                    if (DOTS == 1) ed[rows[s] * 4 + h] = e2[s];
                }
            }
        }
    }

    if (C != nullptr) {
        #pragma unroll
        for (int ma = 0; ma < 2; ma++) {
            int r0 = rbase + ma * 16 + g;
            #pragma unroll
            for (int na = 0; na < 8; na++) {
                int col = n0 + wn * 64 + na * 8 + 2 * t;
                if (r0 < M) {
                    float2 v; v.x = acc[ma][na][0]; v.y = acc[ma][na][1];
                    *(float2*)&C[(size_t)r0 * Nld + col] = v;
                }
                if (r0 + 8 < M) {
                    float2 v; v.x = acc[ma][na][2]; v.y = acc[ma][na][3];
                    *(float2*)&C[(size_t)(r0 + 8) * Nld + col] = v;
                }
            }
        }
    }
}

// ---------------- weight repack: W[h][f][d] -> out[(h*64+d)][f] ----------------
__global__ void pack_headwise(const float* __restrict__ W, float* __restrict__ out) {
    int o = blockIdx.x * 256 + threadIdx.x;
    int n = o >> 8, f = o & 255;
    int h = n >> 6, dd = n & 63;
    out[o] = W[(h * 256 + f) * 64 + dd];
}

// vmat[f][h] = sum_d W_cross[h][f][d] * a_cross[h][64+d]
__global__ void compute_vmat(const float* __restrict__ Wc, const float* __restrict__ ac,
                             float* __restrict__ vmat) {
    int tid = blockIdx.x * 256 + threadIdx.x;   // 0..1023
    int f = tid >> 2, h = tid & 3;
    float s = 0.f;
    #pragma unroll 8
    for (int dd = 0; dd < 64; dd++)
        s = fmaf(Wc[(h * 256 + f) * 64 + dd], ac[h * 128 + 64 + dd], s);
    vmat[f * 4 + h] = s;
}

// ---------------- intra-turn GAT aggregation (deg 16) + fused edX ----------------
__global__ __launch_bounds__(256)
void intra_agg(const float* __restrict__ Wh, const float* __restrict__ es,
               const float* __restrict__ ed, const float* __restrict__ ab,
               const int* __restrict__ src, const float* __restrict__ vmat,
               float* __restrict__ x, float* __restrict__ edX) {
    int d = blockIdx.x;
    int tid = threadIdx.x;
    int lane = tid & 31, wid = tid >> 5;
    __shared__ int   s_src[DEG_IN];
    __shared__ float se[NHEADS * DEG_IN];
    __shared__ float sred[8 * NHEADS];

    if (tid < DEG_IN) s_src[tid] = src[d * DEG_IN + tid];
    __syncthreads();

    if (tid < NHEADS * DEG_IN) {
        int i = tid & 15, h = tid >> 4;
        float e = es[s_src[i] * NHEADS + h] + ed[d * NHEADS + h] + ab[h];
        se[tid] = (e >= 0.f) ? e : ALPHA * e;
    }
    __syncthreads();

    if (tid < NHEADS) {
        float m = -1e30f;
        #pragma unroll
        for (int i = 0; i < DEG_IN; i++) m = fmaxf(m, se[tid * DEG_IN + i]);
        float s = 0.f;
        #pragma unroll
        for (int i = 0; i < DEG_IN; i++) {
            float ex = expf(se[tid * DEG_IN + i] - m);
            se[tid * DEG_IN + i] = ex;
            s += ex;
        }
        float inv = 1.f / fmaxf(s, 1e-9f);
        #pragma unroll
        for (int i = 0; i < DEG_IN; i++) se[tid * DEG_IN + i] *= inv;
    }
    __syncthreads();

    int h = tid >> 6;
    float acc = 0.f;
    #pragma unroll
    for (int i = 0; i < DEG_IN; i++)
        acc = fmaf(se[h * DEG_IN + i], Wh[s_src[i] * NHID + tid], acc);
    x[d * NHID + tid] = acc;

    // fused edX[d][h'] = sum_f x[d][f] * vmat[f][h']
    float4 vm = *(const float4*)&vmat[tid * 4];
    float p0 = acc * vm.x, p1 = acc * vm.y, p2 = acc * vm.z, p3 = acc * vm.w;
    #pragma unroll
    for (int off = 16; off > 0; off >>= 1) {
        p0 += __shfl_xor_sync(0xffffffffu, p0, off);
        p1 += __shfl_xor_sync(0xffffffffu, p1, off);
        p2 += __shfl_xor_sync(0xffffffffu, p2, off);
        p3 += __shfl_xor_sync(0xffffffffu, p3, off);
    }
    if (lane == 0) {
        sred[wid * 4 + 0] = p0;
        sred[wid * 4 + 1] = p1;
        sred[wid * 4 + 2] = p2;
        sred[wid * 4 + 3] = p3;
    }
    __syncthreads();
    if (tid < NHEADS) {
        float s = 0.f;
        #pragma unroll
        for (int w = 0; w < 8; w++) s += sred[w * 4 + tid];
        edX[d * NHEADS + tid] = s;
    }
}

// ---------------- cross-turn GAT (counter + support fused) ----------------
__global__ __launch_bounds__(256)
void cross_agg(const float* __restrict__ Whp, const float* __restrict__ esP,
               const float* __restrict__ edX, const int* __restrict__ src_c,
               const int* __restrict__ src_s, float* __restrict__ hout) {
    int d = blockIdx.x;
    int tid = threadIdx.x;
    __shared__ int   sc[DEG_C], ss[DEG_C];
    __shared__ float se[2 * NHEADS * DEG_C];

    if (tid < DEG_C)           sc[tid]         = src_c[d * DEG_C + tid];
    else if (tid < 2 * DEG_C)  ss[tid - DEG_C] = src_s[d * DEG_C + (tid - DEG_C)];
    __syncthreads();

    if (tid < 64) {
        int which = tid >> 5;
        int tt = tid & 31;
        int i = tt & 7, h = tt >> 3;
        int s = which ? ss[i] : sc[i];
        float e = esP[s * NHEADS + h] + edX[d * NHEADS + h];
        se[tid] = (e >= 0.f) ? e : ALPHA * e;
    }
    __syncthreads();

    if (tid < 8) {
        float* ep = &se[(tid >> 2) * 32 + (tid & 3) * 8];
        float m = -1e30f;
        #pragma unroll
        for (int i = 0; i < DEG_C; i++) m = fmaxf(m, ep[i]);
        float s = 0.f;
        #pragma unroll
        for (int i = 0; i < DEG_C; i++) { float ex = expf(ep[i] - m); ep[i] = ex; s += ex; }
        float inv = 1.f / fmaxf(s, 1e-9f);
        #pragma unroll
        for (int i = 0; i < DEG_C; i++) ep[i] *= inv;
    }
    __syncthreads();

    int h = tid >> 6;
    float acc = 0.f;
    #pragma unroll
    for (int i = 0; i < DEG_C; i++)
        acc = fmaf(se[h * DEG_C + i], Whp[sc[i] * NHID + tid], acc);
    #pragma unroll
    for (int i = 0; i < DEG_C; i++)
        acc = fmaf(se[32 + h * DEG_C + i], Whp[ss[i] * NHID + tid], acc);
    hout[d * NHID + tid] = 0.5f * acc;
}

// ---------------- GRU elementwise ----------------
__global__ void gru_kernel(const float* __restrict__ gi, const float* __restrict__ gh,
                           const float* __restrict__ h, float* __restrict__ out) {
    int idx = blockIdx.x * 256 + threadIdx.x;
    int node = idx >> 8, c = idx & 255;
    const float* gip = gi + (size_t)node * 768;
    const float* ghp = gh + (size_t)node * 768;
    float r = 1.f / (1.f + expf(-(gip[c]       + ghp[c])));
    float z = 1.f / (1.f + expf(-(gip[256 + c] + ghp[256 + c])));
    float nn = tanhf(gip[512 + c] + r * ghp[512 + c]);
    out[idx] = (1.f - z) * nn + z * h[idx];
}

// ---------------- host launcher ----------------
extern "C" void kernel_launch(void* const* d_in, const int* in_sizes, int n_in,
                              void* d_out, int out_size) {
    const float* h_t      = (const float*)d_in[0];
    const float* h_prev   = (const float*)d_in[1];
    const float* W_intra  = (const float*)d_in[2];
    const float* b_intra  = (const float*)d_in[3];
    const float* a_intra  = (const float*)d_in[4];
    const float* ab_intra = (const float*)d_in[5];
    const float* W_cross  = (const float*)d_in[6];
    const float* a_cross  = (const float*)d_in[7];
    const float* W_ih     = (const float*)d_in[8];
    const float* W_hh     = (const float*)d_in[9];
    const float* b_ih     = (const float*)d_in[10];
    const float* b_hh     = (const float*)d_in[11];
    const int*   src_in   = (const int*)d_in[12];
    const int*   src_c    = (const int*)d_in[14];
    const int*   src_s    = (const int*)d_in[16];
    float* out = (float*)d_out;

    float *p_Wh, *p_x, *p_Whp, *p_h, *p_gi, *p_gh;
    float *p_pki, *p_pkc, *p_vm, *p_es, *p_ed, *p_esP, *p_edX;
    cudaGetSymbolAddress((void**)&p_Wh,  d_Wh);
    cudaGetSymbolAddress((void**)&p_x,   d_x);
    cudaGetSymbolAddress((void**)&p_Whp, d_Whp);
    cudaGetSymbolAddress((void**)&p_h,   d_h);
    cudaGetSymbolAddress((void**)&p_gi,  d_gi);
    cudaGetSymbolAddress((void**)&p_gh,  d_gh);
    cudaGetSymbolAddress((void**)&p_pki, d_pk_intra);
    cudaGetSymbolAddress((void**)&p_pkc, d_pk_cross);
    cudaGetSymbolAddress((void**)&p_vm,  d_vmat);
    cudaGetSymbolAddress((void**)&p_es,  d_es);
    cudaGetSymbolAddress((void**)&p_ed,  d_ed);
    cudaGetSymbolAddress((void**)&p_esP, d_esP);
    cudaGetSymbolAddress((void**)&p_edX, d_edX);

    cudaFuncSetAttribute(gemm_mma<1,1>, cudaFuncAttributeMaxDynamicSharedMemorySize, SMEM_SPLIT);
    cudaFuncSetAttribute(gemm_mma<2,1>, cudaFuncAttributeMaxDynamicSharedMemorySize, SMEM_SPLIT);
    cudaFuncSetAttribute(gemm_mma<0,0>, cudaFuncAttributeMaxDynamicSharedMemorySize, SMEM_PLAIN);

    // 1. repack weights + vmat
    pack_headwise<<<256, 256>>>(W_intra, p_pki);
    pack_headwise<<<256, 256>>>(W_cross, p_pkc);
    compute_vmat<<<4, 256>>>(W_cross, a_cross, p_vm);

    dim3 g2((NN + BMM - 1) / BMM, 2);
    dim3 g6((NN + BMM - 1) / BMM, 6);

    // 2. Wh = h_t @ W_intra^T + b (split, fused es/ed)
    gemm_mma<1,1><<<g2, 256, SMEM_SPLIT>>>(h_t, p_pki, b_intra, a_intra,
                                           p_Wh, p_es, p_ed, NN, NHID);
    // 3. Whp = h_prev @ W_cross^T (split, fused esP)
    gemm_mma<2,1><<<g2, 256, SMEM_SPLIT>>>(h_prev, p_pkc, nullptr, a_cross,
                                           p_Whp, p_esP, nullptr, NPREV, NHID);
    // 4. intra GAT -> x (+ fused edX matvec; Whx GEMM eliminated)
    intra_agg<<<NN, 256>>>(p_Wh, p_es, p_ed, ab_intra, src_in, p_vm, p_x, p_edX);
    // 5. cross GAT -> h
    cross_agg<<<NN, 256>>>(p_Whp, p_esP, p_edX, src_c, src_s, p_h);
    // 6. GRU gate GEMMs (plain tf32)
    gemm_mma<0,0><<<g6, 256, SMEM_PLAIN>>>(p_x, W_ih, b_ih, nullptr,
                                           p_gi, nullptr, nullptr, NN, 3 * NHID);
    gemm_mma<0,0><<<g6, 256, SMEM_PLAIN>>>(p_h, W_hh, b_hh, nullptr,
                                           p_gh, nullptr, nullptr, NN, 3 * NHID);
    // 7. GRU elementwise -> out
    gru_kernel<<<NN, 256>>>(p_gi, p_gh, p_h, out);
}

// round 5
// speedup vs baseline: 1.2673x; 1.2673x over previous
#include <cuda_runtime.h>
#include <cuda_bf16.h>
#include <math.h>
#include <stdint.h>

// ---------------- problem constants ----------------
#define NN      50000
#define NPREV   50000
#define NFEATS  256
#define NHID    256
#define NHEADS  4
#define HD      64
#define DEG_IN  16
#define DEG_C   8
#define ALPHA   0.2f

// ---------------- device scratch ----------------
__device__ float d_Wh  [NN * NHID];
__device__ float d_x   [NN * NHID];
__device__ float d_Whp [NPREV * NHID];
__device__ float d_h   [NN * NHID];
__device__ float d_grz [NN * 512];          // gi+gh for r,z gates
__device__ float d_gin [NN * NHID];         // gi n-gate
__device__ float d_ghn [NN * NHID];         // gh n-gate
__device__ float d_pk_intra[NHID * NFEATS]; // [n][k]
__device__ float d_pk_cross[NHID * NHID];
__device__ float d_vmat[NFEATS * NHEADS];
__device__ float d_es [NN * NHEADS];
__device__ float d_ed [NN * NHEADS];
__device__ float d_esP[NPREV * NHEADS];
__device__ float d_edX[NN * NHEADS];

// ---------------- helpers ----------------
__device__ __forceinline__ uint32_t f2tf32(float x) {
    uint32_t r;
    asm("cvt.rna.tf32.f32 %0, %1;" : "=r"(r) : "f"(x));
    return r;
}
__device__ __forceinline__ void mma_tf32(float* d, const uint32_t* a, const uint32_t* b) {
    asm volatile(
        "mma.sync.aligned.m16n8k8.row.col.f32.tf32.tf32.f32 "
        "{%0,%1,%2,%3},{%4,%5,%6,%7},{%8,%9},{%0,%1,%2,%3};"
        : "+f"(d[0]), "+f"(d[1]), "+f"(d[2]), "+f"(d[3])
        : "r"(a[0]), "r"(a[1]), "r"(a[2]), "r"(a[3]), "r"(b[0]), "r"(b[1]));
}
__device__ __forceinline__ uint4 cvt4(float4 v) {
    uint4 o;
    o.x = f2tf32(v.x); o.y = f2tf32(v.y); o.z = f2tf32(v.z); o.w = f2tf32(v.w);
    return o;
}
__device__ __forceinline__ uint4 cvt4lo(float4 v, uint4 hi) {
    uint4 o;
    o.x = f2tf32(v.x - __uint_as_float(hi.x));
    o.y = f2tf32(v.y - __uint_as_float(hi.y));
    o.z = f2tf32(v.z - __uint_as_float(hi.z));
    o.w = f2tf32(v.w - __uint_as_float(hi.w));
    return o;
}

// ---------------- GEMM: padded row-major staging, staged tf32 conversion ------
// C[M, Nld] cols [n0,n0+128) = A[M,256] @ B[n][k]^T + bias
// SPLIT=1: A hi+lo (fp32-accurate). DOTS: 0 none, 1 es+ed, 2 es only.
#define BMM 128
#define LDP 36
#define PLW (128 * LDP)                 // words per plane (4608)
#define SMEM_SPLIT (3 * PLW * 4)        // 55296
#define SMEM_PLAIN (2 * PLW * 4)        // 36864

template<int DOTS, int SPLIT>
__global__ void __launch_bounds__(256, 2)
gemm_mma(const float* __restrict__ A, const float* __restrict__ B,
         const float* __restrict__ bias, const float* __restrict__ avec,
         float* __restrict__ C, float* __restrict__ es, float* __restrict__ ed,
         int M, int Nld) {
    extern __shared__ char smem[];
    uint32_t* sAhi = (uint32_t*)smem;
    uint32_t* sB   = sAhi + PLW;
    uint32_t* sAlo = sAhi + 2 * PLW;

    const int tid = threadIdx.x;
    const int wid = tid >> 5, lane = tid & 31;
    const int wm = wid & 3, wn = wid >> 2;
    const int g = lane >> 2, t = lane & 3;
    const int m0 = blockIdx.x * BMM;
    const int n0 = blockIdx.y * BMM;
    const int rb = tid >> 3, c4 = tid & 7;

    float acc[2][8][4];
    #pragma unroll
    for (int ma = 0; ma < 2; ma++)
        #pragma unroll
        for (int na = 0; na < 8; na++)
            #pragma unroll
            for (int q = 0; q < 4; q++) acc[ma][na][q] = 0.f;

    float4 pa[4], pb[4];
    #pragma unroll
    for (int j = 0; j < 4; j++) {
        int r = rb + j * 32;
        int row = m0 + r; if (row >= M) row = M - 1;
        pa[j] = *(const float4*)&A[(size_t)row * 256 + c4 * 4];
        pb[j] = *(const float4*)&B[(size_t)(n0 + r) * 256 + c4 * 4];
    }

    for (int cc = 0; cc < 8; cc++) {
        if (cc > 0) __syncthreads();
        #pragma unroll
        for (int j = 0; j < 4; j++) {
            int r = rb + j * 32;
            uint32_t w = r * LDP + c4 * 4;
            uint4 hi = cvt4(pa[j]);
            *(uint4*)&sAhi[w] = hi;
            if (SPLIT) *(uint4*)&sAlo[w] = cvt4lo(pa[j], hi);
            *(uint4*)&sB[w] = cvt4(pb[j]);
        }
        __syncthreads();
        if (cc < 7) {
            #pragma unroll
            for (int j = 0; j < 4; j++) {
                int r = rb + j * 32;
                int row = m0 + r; if (row >= M) row = M - 1;
                pa[j] = *(const float4*)&A[(size_t)row * 256 + (cc + 1) * 32 + c4 * 4];
                pb[j] = *(const float4*)&B[(size_t)(n0 + r) * 256 + (cc + 1) * 32 + c4 * 4];
            }
        }
        #pragma unroll
        for (int ks = 0; ks < 4; ks++) {
            int c0 = ks * 8 + t;
            uint32_t aHi[2][4], aLo[2][4];
            #pragma unroll
            for (int ma = 0; ma < 2; ma++) {
                int r0 = wm * 32 + ma * 16 + g;
                aHi[ma][0] = sAhi[r0 * LDP + c0];
                aHi[ma][1] = sAhi[(r0 + 8) * LDP + c0];
                aHi[ma][2] = sAhi[r0 * LDP + c0 + 4];
                aHi[ma][3] = sAhi[(r0 + 8) * LDP + c0 + 4];
                if (SPLIT) {
                    aLo[ma][0] = sAlo[r0 * LDP + c0];
                    aLo[ma][1] = sAlo[(r0 + 8) * LDP + c0];
                    aLo[ma][2] = sAlo[r0 * LDP + c0 + 4];
                    aLo[ma][3] = sAlo[(r0 + 8) * LDP + c0 + 4];
                }
            }
            #pragma unroll
            for (int na = 0; na < 8; na++) {
                int br = wn * 64 + na * 8 + g;
                uint32_t bb[2];
                bb[0] = sB[br * LDP + c0];
                bb[1] = sB[br * LDP + c0 + 4];
                #pragma unroll
                for (int ma = 0; ma < 2; ma++) {
                    mma_tf32(acc[ma][na], aHi[ma], bb);
                    if (SPLIT) mma_tf32(acc[ma][na], aLo[ma], bb);
                }
            }
        }
    }

    if (bias != nullptr) {
        #pragma unroll
        for (int na = 0; na < 8; na++)
            #pragma unroll
            for (int j = 0; j < 2; j++) {
                float bv = __ldg(&bias[n0 + wn * 64 + na * 8 + 2 * t + j]);
                acc[0][na][j]     += bv;
                acc[0][na][2 + j] += bv;
                acc[1][na][j]     += bv;
                acc[1][na][2 + j] += bv;
            }
    }

    int rbase = m0 + wm * 32;

    if (DOTS != 0) {
        int h = blockIdx.y * 2 + wn;
        float e1[4] = {0.f, 0.f, 0.f, 0.f};
        float e2[4] = {0.f, 0.f, 0.f, 0.f};
        #pragma unroll
        for (int na = 0; na < 8; na++)
            #pragma unroll
            for (int j = 0; j < 2; j++) {
                int cw = na * 8 + 2 * t + j;
                float a1 = __ldg(&avec[h * 128 + cw]);
                float a2 = __ldg(&avec[h * 128 + 64 + cw]);
                e1[0] = fmaf(acc[0][na][j], a1, e1[0]);
                e1[1] = fmaf(acc[0][na][2 + j], a1, e1[1]);
                e1[2] = fmaf(acc[1][na][j], a1, e1[2]);
                e1[3] = fmaf(acc[1][na][2 + j], a1, e1[3]);
                e2[0] = fmaf(acc[0][na][j], a2, e2[0]);
                e2[1] = fmaf(acc[0][na][2 + j], a2, e2[1]);
                e2[2] = fmaf(acc[1][na][j], a2, e2[2]);
                e2[3] = fmaf(acc[1][na][2 + j], a2, e2[3]);
            }
        #pragma unroll
        for (int s = 0; s < 4; s++) {
            e1[s] += __shfl_xor_sync(0xffffffffu, e1[s], 1);
            e1[s] += __shfl_xor_sync(0xffffffffu, e1[s], 2);
            e2[s] += __shfl_xor_sync(0xffffffffu, e2[s], 1);
            e2[s] += __shfl_xor_sync(0xffffffffu, e2[s], 2);
        }
        if (t == 0) {
            int rows[4] = {rbase + g, rbase + 8 + g, rbase + 16 + g, rbase + 24 + g};
            #pragma unroll
            for (int s = 0; s < 4; s++) {
                if (rows[s] < M) {
                    es[rows[s] * 4 + h] = e1[s];
                    if (DOTS == 1) ed[rows[s] * 4 + h] = e2[s];
                }
            }
        }
    }

    if (C != nullptr) {
        #pragma unroll
        for (int ma = 0; ma < 2; ma++) {
            int r0 = rbase + ma * 16 + g;
            #pragma unroll
            for (int na = 0; na < 8; na++) {
                int col = n0 + wn * 64 + na * 8 + 2 * t;
                if (r0 < M) {
                    float2 v; v.x = acc[ma][na][0]; v.y = acc[ma][na][1];
                    *(float2*)&C[(size_t)r0 * Nld + col] = v;
                }
                if (r0 + 8 < M) {
                    float2 v; v.x = acc[ma][na][2]; v.y = acc[ma][na][3];
                    *(float2*)&C[(size_t)(r0 + 8) * Nld + col] = v;
                }
            }
        }
    }
}

// ---------------- fused r/z gate GEMM: grz = x@Wih_rz^T + h@Whh_rz^T + b -------
// concat-K = 512 (chunks 0-7 from x/Wih, 8-15 from h/Whh); cols n0 in [0,512)
__global__ void __launch_bounds__(256, 2)
gemm_gate(const float* __restrict__ X, const float* __restrict__ H,
          const float* __restrict__ Wih, const float* __restrict__ Whh,
          const float* __restrict__ bih, const float* __restrict__ bhh,
          float* __restrict__ C, int M) {
    extern __shared__ char smem[];
    uint32_t* sA = (uint32_t*)smem;
    uint32_t* sB = sA + PLW;

    const int tid = threadIdx.x;
    const int wid = tid >> 5, lane = tid & 31;
    const int wm = wid & 3, wn = wid >> 2;
    const int g = lane >> 2, t = lane & 3;
    const int m0 = blockIdx.x * BMM;
    const int n0 = blockIdx.y * BMM;
    const int rb = tid >> 3, c4 = tid & 7;

    float acc[2][8][4];
    #pragma unroll
    for (int ma = 0; ma < 2; ma++)
        #pragma unroll
        for (int na = 0; na < 8; na++)
            #pragma unroll
            for (int q = 0; q < 4; q++) acc[ma][na][q] = 0.f;

    float4 pa[4], pb[4];
    #pragma unroll
    for (int j = 0; j < 4; j++) {
        int r = rb + j * 32;
        int row = m0 + r; if (row >= M) row = M - 1;
        pa[j] = *(const float4*)&X[(size_t)row * 256 + c4 * 4];
        pb[j] = *(const float4*)&Wih[(size_t)(n0 + r) * 256 + c4 * 4];
    }

    for (int cc = 0; cc < 16; cc++) {
        if (cc > 0) __syncthreads();
        #pragma unroll
        for (int j = 0; j < 4; j++) {
            int r = rb + j * 32;
            uint32_t w = r * LDP + c4 * 4;
            *(uint4*)&sA[w] = cvt4(pa[j]);
            *(uint4*)&sB[w] = cvt4(pb[j]);
        }
        __syncthreads();
        if (cc < 15) {
            int nc = cc + 1;
            const float* Ap = (nc < 8) ? X : H;
            const float* Bp = (nc < 8) ? Wih : Whh;
            int kk = (nc & 7) * 32;
            #pragma unroll
            for (int j = 0; j < 4; j++) {
                int r = rb + j * 32;
                int row = m0 + r; if (row >= M) row = M - 1;
                pa[j] = *(const float4*)&Ap[(size_t)row * 256 + kk + c4 * 4];
                pb[j] = *(const float4*)&Bp[(size_t)(n0 + r) * 256 + kk + c4 * 4];
            }
        }
        #pragma unroll
        for (int ks = 0; ks < 4; ks++) {
            int c0 = ks * 8 + t;
            uint32_t aF[2][4];
            #pragma unroll
            for (int ma = 0; ma < 2; ma++) {
                int r0 = wm * 32 + ma * 16 + g;
                aF[ma][0] = sA[r0 * LDP + c0];
                aF[ma][1] = sA[(r0 + 8) * LDP + c0];
                aF[ma][2] = sA[r0 * LDP + c0 + 4];
                aF[ma][3] = sA[(r0 + 8) * LDP + c0 + 4];
            }
            #pragma unroll
            for (int na = 0; na < 8; na++) {
                int br = wn * 64 + na * 8 + g;
                uint32_t bb[2];
                bb[0] = sB[br * LDP + c0];
                bb[1] = sB[br * LDP + c0 + 4];
                #pragma unroll
                for (int ma = 0; ma < 2; ma++)
                    mma_tf32(acc[ma][na], aF[ma], bb);
            }
        }
    }

    int rbase = m0 + wm * 32;
    #pragma unroll
    for (int ma = 0; ma < 2; ma++) {
        int r0 = rbase + ma * 16 + g;
        #pragma unroll
        for (int na = 0; na < 8; na++) {
            int col = n0 + wn * 64 + na * 8 + 2 * t;
            float b0 = __ldg(&bih[col]) + __ldg(&bhh[col]);
            float b1 = __ldg(&bih[col + 1]) + __ldg(&bhh[col + 1]);
            if (r0 < M) {
                float2 v; v.x = acc[ma][na][0] + b0; v.y = acc[ma][na][1] + b1;
                *(float2*)&C[(size_t)r0 * 512 + col] = v;
            }
            if (r0 + 8 < M) {
                float2 v; v.x = acc[ma][na][2] + b0; v.y = acc[ma][na][3] + b1;
                *(float2*)&C[(size_t)(r0 + 8) * 512 + col] = v;
            }
        }
    }
}

// ---------------- weight repack: W[h][f][d] -> out[(h*64+d)][f] ----------------
__global__ void pack_headwise(const float* __restrict__ W, float* __restrict__ out) {
    int o = blockIdx.x * 256 + threadIdx.x;
    int n = o >> 8, f = o & 255;
    int h = n >> 6, dd = n & 63;
    out[o] = W[(h * 256 + f) * 64 + dd];
}

// vmat[f][h] = sum_d W_cross[h][f][d] * a_cross[h][64+d]
__global__ void compute_vmat(const float* __restrict__ Wc, const float* __restrict__ ac,
                             float* __restrict__ vmat) {
    int tid = blockIdx.x * 256 + threadIdx.x;
    int f = tid >> 2, h = tid & 3;
    float s = 0.f;
    #pragma unroll 8
    for (int dd = 0; dd < 64; dd++)
        s = fmaf(Wc[(h * 256 + f) * 64 + dd], ac[h * 128 + 64 + dd], s);
    vmat[f * 4 + h] = s;
}

// ---------------- intra-turn GAT aggregation + fused edX ----------------
__global__ __launch_bounds__(256)
void intra_agg(const float* __restrict__ Wh, const float* __restrict__ es,
               const float* __restrict__ ed, const float* __restrict__ ab,
               const int* __restrict__ src, const float* __restrict__ vmat,
               float* __restrict__ x, float* __restrict__ edX) {
    int d = blockIdx.x;
    int tid = threadIdx.x;
    int lane = tid & 31, wid = tid >> 5;
    __shared__ int   s_src[DEG_IN];
    __shared__ float se[NHEADS * DEG_IN];
    __shared__ float sred[8 * NHEADS];

    if (tid < DEG_IN) s_src[tid] = src[d * DEG_IN + tid];
    __syncthreads();

    if (tid < NHEADS * DEG_IN) {
        int i = tid & 15, h = tid >> 4;
        float e = es[s_src[i] * NHEADS + h] + ed[d * NHEADS + h] + ab[h];
        se[tid] = (e >= 0.f) ? e : ALPHA * e;
    }
    __syncthreads();

    if (tid < NHEADS) {
        float m = -1e30f;
        #pragma unroll
        for (int i = 0; i < DEG_IN; i++) m = fmaxf(m, se[tid * DEG_IN + i]);
        float s = 0.f;
        #pragma unroll
        for (int i = 0; i < DEG_IN; i++) {
            float ex = expf(se[tid * DEG_IN + i] - m);
            se[tid * DEG_IN + i] = ex;
            s += ex;
        }
        float inv = 1.f / fmaxf(s, 1e-9f);
        #pragma unroll
        for (int i = 0; i < DEG_IN; i++) se[tid * DEG_IN + i] *= inv;
    }
    __syncthreads();

    int h = tid >> 6;
    float acc = 0.f;
    #pragma unroll
    for (int i = 0; i < DEG_IN; i++)
        acc = fmaf(se[h * DEG_IN + i], Wh[s_src[i] * NHID + tid], acc);
    x[d * NHID + tid] = acc;

    float4 vm = *(const float4*)&vmat[tid * 4];
    float p0 = acc * vm.x, p1 = acc * vm.y, p2 = acc * vm.z, p3 = acc * vm.w;
    #pragma unroll
    for (int off = 16; off > 0; off >>= 1) {
        p0 += __shfl_xor_sync(0xffffffffu, p0, off);
        p1 += __shfl_xor_sync(0xffffffffu, p1, off);
        p2 += __shfl_xor_sync(0xffffffffu, p2, off);
        p3 += __shfl_xor_sync(0xffffffffu, p3, off);
    }
    if (lane == 0) {
        sred[wid * 4 + 0] = p0;
        sred[wid * 4 + 1] = p1;
        sred[wid * 4 + 2] = p2;
        sred[wid * 4 + 3] = p3;
    }
    __syncthreads();
    if (tid < NHEADS) {
        float s = 0.f;
        #pragma unroll
        for (int w = 0; w < 8; w++) s += sred[w * 4 + tid];
        edX[d * NHEADS + tid] = s;
    }
}

// ---------------- cross-turn GAT (counter + support fused) ----------------
__global__ __launch_bounds__(256)
void cross_agg(const float* __restrict__ Whp, const float* __restrict__ esP,
               const float* __restrict__ edX, const int* __restrict__ src_c,
               const int* __restrict__ src_s, float* __restrict__ hout) {
    int d = blockIdx.x;
    int tid = threadIdx.x;
    __shared__ int   sc[DEG_C], ss[DEG_C];
    __shared__ float se[2 * NHEADS * DEG_C];

    if (tid < DEG_C)           sc[tid]         = src_c[d * DEG_C + tid];
    else if (tid < 2 * DEG_C)  ss[tid - DEG_C] = src_s[d * DEG_C + (tid - DEG_C)];
    __syncthreads();

    if (tid < 64) {
        int which = tid >> 5;
        int tt = tid & 31;
        int i = tt & 7, h = tt >> 3;
        int s = which ? ss[i] : sc[i];
        float e = esP[s * NHEADS + h] + edX[d * NHEADS + h];
        se[tid] = (e >= 0.f) ? e : ALPHA * e;
    }
    __syncthreads();

    if (tid < 8) {
        float* ep = &se[(tid >> 2) * 32 + (tid & 3) * 8];
        float m = -1e30f;
        #pragma unroll
        for (int i = 0; i < DEG_C; i++) m = fmaxf(m, ep[i]);
        float s = 0.f;
        #pragma unroll
        for (int i = 0; i < DEG_C; i++) { float ex = expf(ep[i] - m); ep[i] = ex; s += ex; }
        float inv = 1.f / fmaxf(s, 1e-9f);
        #pragma unroll
        for (int i = 0; i < DEG_C; i++) ep[i] *= inv;
    }
    __syncthreads();

    int h = tid >> 6;
    float acc = 0.f;
    #pragma unroll
    for (int i = 0; i < DEG_C; i++)
        acc = fmaf(se[h * DEG_C + i], Whp[sc[i] * NHID + tid], acc);
    #pragma unroll
    for (int i = 0; i < DEG_C; i++)
        acc = fmaf(se[32 + h * DEG_C + i], Whp[ss[i] * NHID + tid], acc);
    hout[d * NHID + tid] = 0.5f * acc;
}

// ---------------- GRU elementwise ----------------
__global__ void gru_kernel(const float* __restrict__ grz, const float* __restrict__ gin,
                           const float* __restrict__ ghn, const float* __restrict__ h,
                           float* __restrict__ out) {
    int idx = blockIdx.x * 256 + threadIdx.x;
    int node = idx >> 8, c = idx & 255;
    float r = 1.f / (1.f + expf(-grz[(size_t)node * 512 + c]));
    float z = 1.f / (1.f + expf(-grz[(size_t)node * 512 + 256 + c]));
    float nn = tanhf(gin[idx] + r * ghn[idx]);
    out[idx] = (1.f - z) * nn + z * h[idx];
}

// ---------------- host launcher ----------------
extern "C" void kernel_launch(void* const* d_in, const int* in_sizes, int n_in,
                              void* d_out, int out_size) {
    const float* h_t      = (const float*)d_in[0];
    const float* h_prev   = (const float*)d_in[1];
    const float* W_intra  = (const float*)d_in[2];
    const float* b_intra  = (const float*)d_in[3];
    const float* a_intra  = (const float*)d_in[4];
    const float* ab_intra = (const float*)d_in[5];
    const float* W_cross  = (const float*)d_in[6];
    const float* a_cross  = (const float*)d_in[7];
    const float* W_ih     = (const float*)d_in[8];
    const float* W_hh     = (const float*)d_in[9];
    const float* b_ih     = (const float*)d_in[10];
    const float* b_hh     = (const float*)d_in[11];
    const int*   src_in   = (const int*)d_in[12];
    const int*   src_c    = (const int*)d_in[14];
    const int*   src_s    = (const int*)d_in[16];
    float* out = (float*)d_out;

    float *p_Wh, *p_x, *p_Whp, *p_h, *p_grz, *p_gin, *p_ghn;
    float *p_pki, *p_pkc, *p_vm, *p_es, *p_ed, *p_esP, *p_edX;
    cudaGetSymbolAddress((void**)&p_Wh,  d_Wh);
    cudaGetSymbolAddress((void**)&p_x,   d_x);
    cudaGetSymbolAddress((void**)&p_Whp, d_Whp);
    cudaGetSymbolAddress((void**)&p_h,   d_h);
    cudaGetSymbolAddress((void**)&p_grz, d_grz);
    cudaGetSymbolAddress((void**)&p_gin, d_gin);
    cudaGetSymbolAddress((void**)&p_ghn, d_ghn);
    cudaGetSymbolAddress((void**)&p_pki, d_pk_intra);
    cudaGetSymbolAddress((void**)&p_pkc, d_pk_cross);
    cudaGetSymbolAddress((void**)&p_vm,  d_vmat);
    cudaGetSymbolAddress((void**)&p_es,  d_es);
    cudaGetSymbolAddress((void**)&p_ed,  d_ed);
    cudaGetSymbolAddress((void**)&p_esP, d_esP);
    cudaGetSymbolAddress((void**)&p_edX, d_edX);

    cudaFuncSetAttribute(gemm_mma<1,1>, cudaFuncAttributeMaxDynamicSharedMemorySize, SMEM_SPLIT);
    cudaFuncSetAttribute(gemm_mma<2,1>, cudaFuncAttributeMaxDynamicSharedMemorySize, SMEM_SPLIT);
    cudaFuncSetAttribute(gemm_mma<0,0>, cudaFuncAttributeMaxDynamicSharedMemorySize, SMEM_PLAIN);
    cudaFuncSetAttribute(gemm_gate,     cudaFuncAttributeMaxDynamicSharedMemorySize, SMEM_PLAIN);

    pack_headwise<<<256, 256>>>(W_intra, p_pki);
    pack_headwise<<<256, 256>>>(W_cross, p_pkc);
    compute_vmat<<<4, 256>>>(W_cross, a_cross, p_vm);

    dim3 g2((NN + BMM - 1) / BMM, 2);
    dim3 g4((NN + BMM - 1) / BMM, 4);

    // Wh = h_t @ W_intra^T + b (split, fused es/ed)
    gemm_mma<1,1><<<g2, 256, SMEM_SPLIT>>>(h_t, p_pki, b_intra, a_intra,
                                           p_Wh, p_es, p_ed, NN, NHID);
    // Whp = h_prev @ W_cross^T (split, fused esP)
    gemm_mma<2,1><<<g2, 256, SMEM_SPLIT>>>(h_prev, p_pkc, nullptr, a_cross,
                                           p_Whp, p_esP, nullptr, NPREV, NHID);
    // intra GAT -> x (+ fused edX)
    intra_agg<<<NN, 256>>>(p_Wh, p_es, p_ed, ab_intra, src_in, p_vm, p_x, p_edX);
    // cross GAT -> h
    cross_agg<<<NN, 256>>>(p_Whp, p_esP, p_edX, src_c, src_s, p_h);
    // fused r/z gates: grz = x@Wih_rz + h@Whh_rz + b  (K=512 concat)
    gemm_gate<<<g4, 256, SMEM_PLAIN>>>(p_x, p_h, W_ih, W_hh, b_ih, b_hh, p_grz, NN);
    // n-gate halves (plain tf32, K=256)
    gemm_mma<0,0><<<g2, 256, SMEM_PLAIN>>>(p_x, W_ih + 512 * 256, b_ih + 512, nullptr,
                                           p_gin, nullptr, nullptr, NN, NHID);
    gemm_mma<0,0><<<g2, 256, SMEM_PLAIN>>>(p_h, W_hh + 512 * 256, b_hh + 512, nullptr,
                                           p_ghn, nullptr, nullptr, NN, NHID);
    // GRU elementwise -> out
    gru_kernel<<<NN, 256>>>(p_grz, p_gin, p_ghn, p_h, out);
}

// round 7
// speedup vs baseline: 1.3528x; 1.0675x over previous
#include <cuda_runtime.h>
#include <cuda_bf16.h>
#include <math.h>
#include <stdint.h>

// ---------------- problem constants ----------------
#define NN      50000
#define NPREV   50000
#define NFEATS  256
#define NHID    256
#define NHEADS  4
#define HD      64
#define DEG_IN  16
#define DEG_C   8
#define ALPHA   0.2f

// ---------------- device scratch ----------------
__device__ float d_Wh  [NN * NHID];
__device__ float d_x   [NN * NHID];
__device__ float d_Whp [NPREV * NHID];
__device__ float d_h   [NN * NHID];
__device__ float d_grz [NN * 512];
__device__ float d_gin [NN * NHID];
__device__ float d_ghn [NN * NHID];
__device__ float d_pk_intra[NHID * NFEATS];   // tf32-rounded, [n][k]
__device__ float d_pk_cross[NHID * NHID];     // tf32-rounded
__device__ float d_pih[768 * 256];            // tf32-rounded W_ih
__device__ float d_phh[768 * 256];            // tf32-rounded W_hh
__device__ float d_vmat[NFEATS * NHEADS];
__device__ float d_es [NN * NHEADS];
__device__ float d_ed [NN * NHEADS];
__device__ float d_esP[NPREV * NHEADS];
__device__ float d_edX[NN * NHEADS];

// ---------------- helpers ----------------
__device__ __forceinline__ uint32_t smem_u32(const void* p) {
    uint32_t a;
    asm("{ .reg .u64 t; cvta.to.shared.u64 t, %1; cvt.u32.u64 %0, t; }" : "=r"(a) : "l"(p));
    return a;
}
__device__ __forceinline__ uint32_t f2tf32(float x) {
    uint32_t r;
    asm("cvt.rna.tf32.f32 %0, %1;" : "=r"(r) : "f"(x));
    return r;
}
__device__ __forceinline__ void cp16(uint32_t dst, const void* src) {
    asm volatile("cp.async.cg.shared.global [%0], [%1], 16;" :: "r"(dst), "l"(src));
}
__device__ __forceinline__ void cp_commit() {
    asm volatile("cp.async.commit_group;" ::: "memory");
}
template<int N>
__device__ __forceinline__ void cp_wait() {
    asm volatile("cp.async.wait_group %0;" :: "n"(N) : "memory");
}
__device__ __forceinline__ void mma_tf32(float* d, const uint32_t* a, const uint32_t* b) {
    asm volatile(
        "mma.sync.aligned.m16n8k8.row.col.f32.tf32.tf32.f32 "
        "{%0,%1,%2,%3},{%4,%5,%6,%7},{%8,%9},{%0,%1,%2,%3};"
        : "+f"(d[0]), "+f"(d[1]), "+f"(d[2]), "+f"(d[3])
        : "r"(a[0]), "r"(a[1]), "r"(a[2]), "r"(a[3]), "r"(b[0]), "r"(b[1]));
}

#define BMM 128
#define LDP 36
#define PLANE_B (128 * LDP * 4)     // 18432
#define STAGE_B (2 * PLANE_B)       // 36864
#define SMEMSZ  (2 * STAGE_B)       // 73728

// staging: cp.async one K=32 slab of A (rows m0..m0+127) and B (rows n0..n0+127)
#define STAGE_CHUNK(Aptr, Bptr, koff, buf)                                        \
do {                                                                              \
    uint32_t abase = sb + (buf) * STAGE_B;                                        \
    uint32_t bbase = abase + PLANE_B;                                             \
    _Pragma("unroll")                                                             \
    for (int j = 0; j < 4; j++) {                                                 \
        int r = (tid >> 3) + j * 32;                                              \
        int row = m0 + r; if (row >= M) row = M - 1;                              \
        cp16(abase + r * (LDP * 4) + (tid & 7) * 16,                              \
             &(Aptr)[(size_t)row * 256 + (koff) + (tid & 7) * 4]);                \
    }                                                                             \
    _Pragma("unroll")                                                             \
    for (int j = 0; j < 4; j++) {                                                 \
        int r = (tid >> 3) + j * 32;                                              \
        cp16(bbase + r * (LDP * 4) + (tid & 7) * 16,                              \
             &(Bptr)[(size_t)(n0 + r) * 256 + (koff) + (tid & 7) * 4]);           \
    }                                                                             \
    cp_commit();                                                                  \
} while (0)

// compute one staged chunk: fragments via scalar LDS; A mask-split (SPLIT) or cvt
#define COMPUTE_CHUNK(buf, DO_SPLIT)                                              \
do {                                                                              \
    const float*    As = (const float*)(smem + (buf) * STAGE_B);                  \
    const uint32_t* Bs = (const uint32_t*)(smem + (buf) * STAGE_B + PLANE_B);     \
    _Pragma("unroll")                                                             \
    for (int ks = 0; ks < 4; ks++) {                                              \
        int c0 = ks * 8 + t;                                                      \
        uint32_t aHi[2][4], aLo[2][4];                                            \
        _Pragma("unroll")                                                         \
        for (int ma = 0; ma < 2; ma++) {                                          \
            int r0 = wm * 32 + ma * 16 + g;                                       \
            float x0 = As[r0 * LDP + c0];                                         \
            float x1 = As[(r0 + 8) * LDP + c0];                                   \
            float x2 = As[r0 * LDP + c0 + 4];                                     \
            float x3 = As[(r0 + 8) * LDP + c0 + 4];                               \
            if (DO_SPLIT) {                                                       \
                aHi[ma][0] = __float_as_uint(x0) & 0xFFFFE000u;                   \
                aHi[ma][1] = __float_as_uint(x1) & 0xFFFFE000u;                   \
                aHi[ma][2] = __float_as_uint(x2) & 0xFFFFE000u;                   \
                aHi[ma][3] = __float_as_uint(x3) & 0xFFFFE000u;                   \
                aLo[ma][0] = __float_as_uint(x0 - __uint_as_float(aHi[ma][0]));   \
                aLo[ma][1] = __float_as_uint(x1 - __uint_as_float(aHi[ma][1]));   \
                aLo[ma][2] = __float_as_uint(x2 - __uint_as_float(aHi[ma][2]));   \
                aLo[ma][3] = __float_as_uint(x3 - __uint_as_float(aHi[ma][3]));   \
            } else {                                                              \
                aHi[ma][0] = f2tf32(x0); aHi[ma][1] = f2tf32(x1);                 \
                aHi[ma][2] = f2tf32(x2); aHi[ma][3] = f2tf32(x3);                 \
            }                                                                     \
        }                                                                         \
        _Pragma("unroll")                                                         \
        for (int na = 0; na < 8; na++) {                                          \
            int br = wn * 64 + na * 8 + g;                                        \
            uint32_t bb[2];                                                       \
            bb[0] = Bs[br * LDP + c0];                                            \
            bb[1] = Bs[br * LDP + c0 + 4];                                        \
            _Pragma("unroll")                                                     \
            for (int ma = 0; ma < 2; ma++) {                                      \
                mma_tf32(acc[ma][na], aHi[ma], bb);                               \
                if (DO_SPLIT) mma_tf32(acc[ma][na], aLo[ma], bb);                 \
            }                                                                     \
        }                                                                         \
    }                                                                             \
} while (0)

// ---------------- GEMM K=256: C cols [n0,n0+128) = A @ B^T + bias ----------------
template<int DOTS, int SPLIT>
__global__ void __launch_bounds__(256, 2)
gemm_mma(const float* __restrict__ A, const float* __restrict__ B,
         const float* __restrict__ bias, const float* __restrict__ avec,
         float* __restrict__ C, float* __restrict__ es, float* __restrict__ ed,
         int M, int Nld) {
    extern __shared__ char smem[];
    uint32_t sb = smem_u32(smem);
    const int tid = threadIdx.x;
    const int wid = tid >> 5, lane = tid & 31;
    const int wm = wid & 3, wn = wid >> 2;
    const int g = lane >> 2, t = lane & 3;
    const int m0 = blockIdx.x * BMM;
    const int n0 = blockIdx.y * BMM;

    float acc[2][8][4];
    #pragma unroll
    for (int ma = 0; ma < 2; ma++)
        #pragma unroll
        for (int na = 0; na < 8; na++)
            #pragma unroll
            for (int q = 0; q < 4; q++) acc[ma][na][q] = 0.f;

    STAGE_CHUNK(A, B, 0, 0);
    for (int cc = 0; cc < 8; cc++) {
        int buf = cc & 1;
        if (cc < 7) { STAGE_CHUNK(A, B, (cc + 1) * 32, buf ^ 1); cp_wait<1>(); }
        else        cp_wait<0>();
        __syncthreads();
        COMPUTE_CHUNK(buf, SPLIT);
        __syncthreads();
    }

    if (bias != nullptr) {
        #pragma unroll
        for (int na = 0; na < 8; na++)
            #pragma unroll
            for (int j = 0; j < 2; j++) {
                float bv = __ldg(&bias[n0 + wn * 64 + na * 8 + 2 * t + j]);
                acc[0][na][j]     += bv;
                acc[0][na][2 + j] += bv;
                acc[1][na][j]     += bv;
                acc[1][na][2 + j] += bv;
            }
    }

    int rbase = m0 + wm * 32;

    if (DOTS != 0) {
        int h = blockIdx.y * 2 + wn;
        float e1[4] = {0.f, 0.f, 0.f, 0.f};
        float e2[4] = {0.f, 0.f, 0.f, 0.f};
        #pragma unroll
        for (int na = 0; na < 8; na++)
            #pragma unroll
            for (int j = 0; j < 2; j++) {
                int cw = na * 8 + 2 * t + j;
                float a1 = __ldg(&avec[h * 128 + cw]);
                float a2 = __ldg(&avec[h * 128 + 64 + cw]);
                e1[0] = fmaf(acc[0][na][j], a1, e1[0]);
                e1[1] = fmaf(acc[0][na][2 + j], a1, e1[1]);
                e1[2] = fmaf(acc[1][na][j], a1, e1[2]);
                e1[3] = fmaf(acc[1][na][2 + j], a1, e1[3]);
                e2[0] = fmaf(acc[0][na][j], a2, e2[0]);
                e2[1] = fmaf(acc[0][na][2 + j], a2, e2[1]);
                e2[2] = fmaf(acc[1][na][j], a2, e2[2]);
                e2[3] = fmaf(acc[1][na][2 + j], a2, e2[3]);
            }
        #pragma unroll
        for (int s = 0; s < 4; s++) {
            e1[s] += __shfl_xor_sync(0xffffffffu, e1[s], 1);
            e1[s] += __shfl_xor_sync(0xffffffffu, e1[s], 2);
            e2[s] += __shfl_xor_sync(0xffffffffu, e2[s], 1);
            e2[s] += __shfl_xor_sync(0xffffffffu, e2[s], 2);
        }
        if (t == 0) {
            int rows[4] = {rbase + g, rbase + 8 + g, rbase + 16 + g, rbase + 24 + g};
            #pragma unroll
            for (int s = 0; s < 4; s++) {
                if (rows[s] < M) {
                    es[rows[s] * 4 + h] = e1[s];
                    if (DOTS == 1) ed[rows[s] * 4 + h] = e2[s];
                }
            }
        }
    }

    if (C != nullptr) {
        #pragma unroll
        for (int ma = 0; ma < 2; ma++) {
            int r0 = rbase + ma * 16 + g;
            #pragma unroll
            for (int na = 0; na < 8; na++) {
                int col = n0 + wn * 64 + na * 8 + 2 * t;
                if (r0 < M) {
                    float2 v; v.x = acc[ma][na][0]; v.y = acc[ma][na][1];
                    *(float2*)&C[(size_t)r0 * Nld + col] = v;
                }
                if (r0 + 8 < M) {
                    float2 v; v.x = acc[ma][na][2]; v.y = acc[ma][na][3];
                    *(float2*)&C[(size_t)(r0 + 8) * Nld + col] = v;
                }
            }
        }
    }
}

// ---------------- fused r/z gate GEMM: grz = x@Wih_rz^T + h@Whh_rz^T + b -------
__global__ void __launch_bounds__(256, 2)
gemm_gate(const float* __restrict__ X, const float* __restrict__ H,
          const float* __restrict__ Wih, const float* __restrict__ Whh,
          const float* __restrict__ bih, const float* __restrict__ bhh,
          float* __restrict__ C, int M) {
    extern __shared__ char smem[];
    uint32_t sb = smem_u32(smem);
    const int tid = threadIdx.x;
    const int wid = tid >> 5, lane = tid & 31;
    const int wm = wid & 3, wn = wid >> 2;
    const int g = lane >> 2, t = lane & 3;
    const int m0 = blockIdx.x * BMM;
    const int n0 = blockIdx.y * BMM;

    float acc[2][8][4];
    #pragma unroll
    for (int ma = 0; ma < 2; ma++)
        #pragma unroll
        for (int na = 0; na < 8; na++)
            #pragma unroll
            for (int q = 0; q < 4; q++) acc[ma][na][q] = 0.f;

    STAGE_CHUNK(X, Wih, 0, 0);
    for (int cc = 0; cc < 16; cc++) {
        int buf = cc & 1;
        if (cc < 15) {
            int nc = cc + 1;
            const float* Ap = (nc < 8) ? X : H;
            const float* Bp = (nc < 8) ? Wih : Whh;
            int koff = (nc & 7) * 32;
            STAGE_CHUNK(Ap, Bp, koff, buf ^ 1);
            cp_wait<1>();
        } else {
            cp_wait<0>();
        }
        __syncthreads();
        COMPUTE_CHUNK(buf, 0);
        __syncthreads();
    }

    int rbase = m0 + wm * 32;
    #pragma unroll
    for (int ma = 0; ma < 2; ma++) {
        int r0 = rbase + ma * 16 + g;
        #pragma unroll
        for (int na = 0; na < 8; na++) {
            int col = n0 + wn * 64 + na * 8 + 2 * t;
            float b0 = __ldg(&bih[col]) + __ldg(&bhh[col]);
            float b1 = __ldg(&bih[col + 1]) + __ldg(&bhh[col + 1]);
            if (r0 < M) {
                float2 v; v.x = acc[ma][na][0] + b0; v.y = acc[ma][na][1] + b1;
                *(float2*)&C[(size_t)r0 * 512 + col] = v;
            }
            if (r0 + 8 < M) {
                float2 v; v.x = acc[ma][na][2] + b0; v.y = acc[ma][na][3] + b1;
                *(float2*)&C[(size_t)(r0 + 8) * 512 + col] = v;
            }
        }
    }
}

// ---------------- packs ----------------
// W[h][f][d] -> out[(h*64+d)][f], tf32-RNA rounded
__global__ void pack_headwise(const float* __restrict__ W, float* __restrict__ out) {
    int o = blockIdx.x * 256 + threadIdx.x;
    int n = o >> 8, f = o & 255;
    int h = n >> 6, dd = n & 63;
    out[o] = __uint_as_float(f2tf32(W[(h * 256 + f) * 64 + dd]));
}
// elementwise tf32-RNA round (W_ih / W_hh, already [n][k])
__global__ void pack_round(const float* __restrict__ W, float* __restrict__ out) {
    int o = blockIdx.x * 256 + threadIdx.x;
    out[o] = __uint_as_float(f2tf32(W[o]));
}
// vmat[f][h] = sum_d W_cross[h][f][d] * a_cross[h][64+d]  (exact fp32)
__global__ void compute_vmat(const float* __restrict__ Wc, const float* __restrict__ ac,
                             float* __restrict__ vmat) {
    int tid = blockIdx.x * 256 + threadIdx.x;
    int f = tid >> 2, h = tid & 3;
    float s = 0.f;
    #pragma unroll 8
    for (int dd = 0; dd < 64; dd++)
        s = fmaf(Wc[(h * 256 + f) * 64 + dd], ac[h * 128 + 64 + dd], s);
    vmat[f * 4 + h] = s;
}

// ---------------- intra-turn GAT aggregation + fused edX ----------------
__global__ __launch_bounds__(256)
void intra_agg(const float* __restrict__ Wh, const float* __restrict__ es,
               const float* __restrict__ ed, const float* __restrict__ ab,
               const int* __restrict__ src, const float* __restrict__ vmat,
               float* __restrict__ x, float* __restrict__ edX) {
    int d = blockIdx.x;
    int tid = threadIdx.x;
    int lane = tid & 31, wid = tid >> 5;
    __shared__ int   s_src[DEG_IN];
    __shared__ float se[NHEADS * DEG_IN];
    __shared__ float sred[8 * NHEADS];

    if (tid < DEG_IN) s_src[tid] = src[d * DEG_IN + tid];
    __syncthreads();

    if (tid < NHEADS * DEG_IN) {
        int i = tid & 15, h = tid >> 4;
        float e = es[s_src[i] * NHEADS + h] + ed[d * NHEADS + h] + ab[h];
        se[tid] = (e >= 0.f) ? e : ALPHA * e;
    }
    __syncthreads();

    if (tid < NHEADS) {
        float m = -1e30f;
        #pragma unroll
        for (int i = 0; i < DEG_IN; i++) m = fmaxf(m, se[tid * DEG_IN + i]);
        float s = 0.f;
        #pragma unroll
        for (int i = 0; i < DEG_IN; i++) {
            float ex = expf(se[tid * DEG_IN + i] - m);
            se[tid * DEG_IN + i] = ex;
            s += ex;
        }
        float inv = 1.f / fmaxf(s, 1e-9f);
        #pragma unroll
        for (int i = 0; i < DEG_IN; i++) se[tid * DEG_IN + i] *= inv;
    }
    __syncthreads();

    int h = tid >> 6;
    float acc = 0.f;
    #pragma unroll
    for (int i = 0; i < DEG_IN; i++)
        acc = fmaf(se[h * DEG_IN + i], Wh[s_src[i] * NHID + tid], acc);
    x[d * NHID + tid] = acc;

    float4 vm = *(const float4*)&vmat[tid * 4];
    float p0 = acc * vm.x, p1 = acc * vm.y, p2 = acc * vm.z, p3 = acc * vm.w;
    #pragma unroll
    for (int off = 16; off > 0; off >>= 1) {
        p0 += __shfl_xor_sync(0xffffffffu, p0, off);
        p1 += __shfl_xor_sync(0xffffffffu, p1, off);
        p2 += __shfl_xor_sync(0xffffffffu, p2, off);
        p3 += __shfl_xor_sync(0xffffffffu, p3, off);
    }
    if (lane == 0) {
        sred[wid * 4 + 0] = p0;
        sred[wid * 4 + 1] = p1;
        sred[wid * 4 + 2] = p2;
        sred[wid * 4 + 3] = p3;
    }
    __syncthreads();
    if (tid < NHEADS) {
        float s = 0.f;
        #pragma unroll
        for (int w = 0; w < 8; w++) s += sred[w * 4 + tid];
        edX[d * NHEADS + tid] = s;
    }
}

// ---------------- cross-turn GAT (counter + support fused) ----------------
__global__ __launch_bounds__(256)
void cross_agg(const float* __restrict__ Whp, const float* __restrict__ esP,
               const float* __restrict__ edX, const int* __restrict__ src_c,
               const int* __restrict__ src_s, float* __restrict__ hout) {
    int d = blockIdx.x;
    int tid = threadIdx.x;
    __shared__ int   sc[DEG_C], ss[DEG_C];
    __shared__ float se[2 * NHEADS * DEG_C];

    if (tid < DEG_C)           sc[tid]         = src_c[d * DEG_C + tid];
    else if (tid < 2 * DEG_C)  ss[tid - DEG_C] = src_s[d * DEG_C + (tid - DEG_C)];
    __syncthreads();

    if (tid < 64) {
        int which = tid >> 5;
        int tt = tid & 31;
        int i = tt & 7, h = tt >> 3;
        int s = which ? ss[i] : sc[i];
        float e = esP[s * NHEADS + h] + edX[d * NHEADS + h];
        se[tid] = (e >= 0.f) ? e : ALPHA * e;
    }
    __syncthreads();

    if (tid < 8) {
        float* ep = &se[(tid >> 2) * 32 + (tid & 3) * 8];
        float m = -1e30f;
        #pragma unroll
        for (int i = 0; i < DEG_C; i++) m = fmaxf(m, ep[i]);
        float s = 0.f;
        #pragma unroll
        for (int i = 0; i < DEG_C; i++) { float ex = expf(ep[i] - m); ep[i] = ex; s += ex; }
        float inv = 1.f / fmaxf(s, 1e-9f);
        #pragma unroll
        for (int i = 0; i < DEG_C; i++) ep[i] *= inv;
    }
    __syncthreads();

    int h = tid >> 6;
    float acc = 0.f;
    #pragma unroll
    for (int i = 0; i < DEG_C; i++)
        acc = fmaf(se[h * DEG_C + i], Whp[sc[i] * NHID + tid], acc);
    #pragma unroll
    for (int i = 0; i < DEG_C; i++)
        acc = fmaf(se[32 + h * DEG_C + i], Whp[ss[i] * NHID + tid], acc);
    hout[d * NHID + tid] = 0.5f * acc;
}

// ---------------- GRU elementwise ----------------
__global__ void gru_kernel(const float* __restrict__ grz, const float* __restrict__ gin,
                           const float* __restrict__ ghn, const float* __restrict__ h,
                           float* __restrict__ out) {
    int idx = blockIdx.x * 256 + threadIdx.x;
    int node = idx >> 8, c = idx & 255;
    float r = 1.f / (1.f + expf(-grz[(size_t)node * 512 + c]));
    float z = 1.f / (1.f + expf(-grz[(size_t)node * 512 + 256 + c]));
    float nn = tanhf(gin[idx] + r * ghn[idx]);
    out[idx] = (1.f - z) * nn + z * h[idx];
}

// ---------------- host launcher ----------------
extern "C" void kernel_launch(void* const* d_in, const int* in_sizes, int n_in,
                              void* d_out, int out_size) {
    const float* h_t      = (const float*)d_in[0];
    const float* h_prev   = (const float*)d_in[1];
    const float* W_intra  = (const float*)d_in[2];
    const float* b_intra  = (const float*)d_in[3];
    const float* a_intra  = (const float*)d_in[4];
    const float* ab_intra = (const float*)d_in[5];
    const float* W_cross  = (const float*)d_in[6];
    const float* a_cross  = (const float*)d_in[7];
    const float* W_ih     = (const float*)d_in[8];
    const float* W_hh     = (const float*)d_in[9];
    const float* b_ih     = (const float*)d_in[10];
    const float* b_hh     = (const float*)d_in[11];
    const int*   src_in   = (const int*)d_in[12];
    const int*   src_c    = (const int*)d_in[14];
    const int*   src_s    = (const int*)d_in[16];
    float* out = (float*)d_out;

    float *p_Wh, *p_x, *p_Whp, *p_h, *p_grz, *p_gin, *p_ghn;
    float *p_pki, *p_pkc, *p_pih, *p_phh, *p_vm, *p_es, *p_ed, *p_esP, *p_edX;
    cudaGetSymbolAddress((void**)&p_Wh,  d_Wh);
    cudaGetSymbolAddress((void**)&p_x,   d_x);
    cudaGetSymbolAddress((void**)&p_Whp, d_Whp);
    cudaGetSymbolAddress((void**)&p_h,   d_h);
    cudaGetSymbolAddress((void**)&p_grz, d_grz);
    cudaGetSymbolAddress((void**)&p_gin, d_gin);
    cudaGetSymbolAddress((void**)&p_ghn, d_ghn);
    cudaGetSymbolAddress((void**)&p_pki, d_pk_intra);
    cudaGetSymbolAddress((void**)&p_pkc, d_pk_cross);
    cudaGetSymbolAddress((void**)&p_pih, d_pih);
    cudaGetSymbolAddress((void**)&p_phh, d_phh);
    cudaGetSymbolAddress((void**)&p_vm,  d_vmat);
    cudaGetSymbolAddress((void**)&p_es,  d_es);
    cudaGetSymbolAddress((void**)&p_ed,  d_ed);
    cudaGetSymbolAddress((void**)&p_esP, d_esP);
    cudaGetSymbolAddress((void**)&p_edX, d_edX);

    cudaFuncSetAttribute(gemm_mma<1,1>, cudaFuncAttributeMaxDynamicSharedMemorySize, SMEMSZ);
    cudaFuncSetAttribute(gemm_mma<2,1>, cudaFuncAttributeMaxDynamicSharedMemorySize, SMEMSZ);
    cudaFuncSetAttribute(gemm_mma<0,0>, cudaFuncAttributeMaxDynamicSharedMemorySize, SMEMSZ);
    cudaFuncSetAttribute(gemm_gate,     cudaFuncAttributeMaxDynamicSharedMemorySize, SMEMSZ);

    // packs: tf32-rounded weights + vmat
    pack_headwise<<<256, 256>>>(W_intra, p_pki);
    pack_headwise<<<256, 256>>>(W_cross, p_pkc);
    pack_round<<<768, 256>>>(W_ih, p_pih);
    pack_round<<<768, 256>>>(W_hh, p_phh);
    compute_vmat<<<4, 256>>>(W_cross, a_cross, p_vm);

    dim3 g2((NN + BMM - 1) / BMM, 2);
    dim3 g4((NN + BMM - 1) / BMM, 4);

    // Wh = h_t @ W_intra^T + b (mask-split A, fused es/ed)
    gemm_mma<1,1><<<g2, 256, SMEMSZ>>>(h_t, p_pki, b_intra, a_intra,
                                       p_Wh, p_es, p_ed, NN, NHID);
    // Whp = h_prev @ W_cross^T (mask-split A, fused esP)
    gemm_mma<2,1><<<g2, 256, SMEMSZ>>>(h_prev, p_pkc, nullptr, a_cross,
                                       p_Whp, p_esP, nullptr, NPREV, NHID);
    // intra GAT -> x (+ fused edX)
    intra_agg<<<NN, 256>>>(p_Wh, p_es, p_ed, ab_intra, src_in, p_vm, p_x, p_edX);
    // cross GAT -> h
    cross_agg<<<NN, 256>>>(p_Whp, p_esP, p_edX, src_c, src_s, p_h);
    // fused r/z gates (K=512 concat)
    gemm_gate<<<g4, 256, SMEMSZ>>>(p_x, p_h, p_pih, p_phh, b_ih, b_hh, p_grz, NN);
    // n-gate halves
    gemm_mma<0,0><<<g2, 256, SMEMSZ>>>(p_x, p_pih + 512 * 256, b_ih + 512, nullptr,
                                       p_gin, nullptr, nullptr, NN, NHID);
    gemm_mma<0,0><<<g2, 256, SMEMSZ>>>(p_h, p_phh + 512 * 256, b_hh + 512, nullptr,
                                       p_ghn, nullptr, nullptr, NN, NHID);
    // GRU elementwise -> out
    gru_kernel<<<NN, 256>>>(p_grz, p_gin, p_ghn, p_h, out);
}

// round 8
// speedup vs baseline: 1.5224x; 1.1253x over previous
#include <cuda_runtime.h>
#include <cuda_bf16.h>
#include <math.h>
#include <stdint.h>

// ---------------- problem constants ----------------
#define NN      50000
#define NPREV   50000
#define NFEATS  256
#define NHID    256
#define NHEADS  4
#define HD      64
#define DEG_IN  16
#define DEG_C   8
#define ALPHA   0.2f

// ---------------- device scratch ----------------
__device__ float d_Wh  [NN * NHID];
__device__ float d_x   [NN * NHID];
__device__ float d_Whp [NPREV * NHID];
__device__ float d_h   [NN * NHID];
__device__ float d_grz [NN * 512];
__device__ float d_gin [NN * NHID];
__device__ float d_ghn [NN * NHID];
__device__ float d_pk_intra[NHID * NFEATS];   // tf32-rounded [n][k]
__device__ float d_pk_cross[NHID * NHID];     // tf32-rounded
__device__ float d_pih[768 * 256];            // tf32-rounded W_ih
__device__ float d_phh[768 * 256];            // tf32-rounded W_hh
__device__ float d_vmat[NFEATS * NHEADS];
__device__ float d_es [NN * NHEADS];
__device__ float d_ed [NN * NHEADS];
__device__ float d_esP[NPREV * NHEADS];
__device__ float d_edX[NN * NHEADS];

// ---------------- helpers ----------------
__device__ __forceinline__ uint32_t smem_u32(const void* p) {
    uint32_t a;
    asm("{ .reg .u64 t; cvta.to.shared.u64 t, %1; cvt.u32.u64 %0, t; }" : "=r"(a) : "l"(p));
    return a;
}
__device__ __forceinline__ uint32_t f2tf32(float x) {
    uint32_t r;
    asm("cvt.rna.tf32.f32 %0, %1;" : "=r"(r) : "f"(x));
    return r;
}
__device__ __forceinline__ void cp16(uint32_t dst, const void* src) {
    asm volatile("cp.async.cg.shared.global [%0], [%1], 16;" :: "r"(dst), "l"(src));
}
__device__ __forceinline__ void cp_commit() {
    asm volatile("cp.async.commit_group;" ::: "memory");
}
template<int N>
__device__ __forceinline__ void cp_wait() {
    asm volatile("cp.async.wait_group %0;" :: "n"(N) : "memory");
}
__device__ __forceinline__ void mma_tf32(float* d, const uint32_t* a, const uint32_t* b) {
    asm volatile(
        "mma.sync.aligned.m16n8k8.row.col.f32.tf32.tf32.f32 "
        "{%0,%1,%2,%3},{%4,%5,%6,%7},{%8,%9},{%0,%1,%2,%3};"
        : "+f"(d[0]), "+f"(d[1]), "+f"(d[2]), "+f"(d[3])
        : "r"(a[0]), "r"(a[1]), "r"(a[2]), "r"(a[3]), "r"(b[0]), "r"(b[1]));
}

#define BMM 128
#define LDP 36
#define PLANE_B (128 * LDP * 4)     // 18432
#define STAGE_B (2 * PLANE_B)
#define SMEMSZ  (2 * STAGE_B)       // 73728

#define STAGE_CHUNK(Aptr, Bptr, koff, buf)                                        \
do {                                                                              \
    uint32_t abase = sb + (buf) * STAGE_B;                                        \
    uint32_t bbase = abase + PLANE_B;                                             \
    _Pragma("unroll")                                                             \
    for (int j = 0; j < 4; j++) {                                                 \
        int r = (tid >> 3) + j * 32;                                              \
        int row = m0 + r; if (row >= M) row = M - 1;                              \
        cp16(abase + r * (LDP * 4) + (tid & 7) * 16,                              \
             &(Aptr)[(size_t)row * 256 + (koff) + (tid & 7) * 4]);                \
    }                                                                             \
    _Pragma("unroll")                                                             \
    for (int j = 0; j < 4; j++) {                                                 \
        int r = (tid >> 3) + j * 32;                                              \
        cp16(bbase + r * (LDP * 4) + (tid & 7) * 16,                              \
             &(Bptr)[(size_t)(n0 + r) * 256 + (koff) + (tid & 7) * 4]);           \
    }                                                                             \
    cp_commit();                                                                  \
} while (0)

#define COMPUTE_CHUNK(buf, DO_SPLIT)                                              \
do {                                                                              \
    const float*    As = (const float*)(smem + (buf) * STAGE_B);                  \
    const uint32_t* Bs = (const uint32_t*)(smem + (buf) * STAGE_B + PLANE_B);     \
    _Pragma("unroll")                                                             \
    for (int ks = 0; ks < 4; ks++) {                                              \
        int c0 = ks * 8 + t;                                                      \
        uint32_t aHi[2][4], aLo[2][4];                                            \
        _Pragma("unroll")                                                         \
        for (int ma = 0; ma < 2; ma++) {                                          \
            int r0 = wm * 32 + ma * 16 + g;                                       \
            float x0 = As[r0 * LDP + c0];                                         \
            float x1 = As[(r0 + 8) * LDP + c0];                                   \
            float x2 = As[r0 * LDP + c0 + 4];                                     \
            float x3 = As[(r0 + 8) * LDP + c0 + 4];                               \
            if (DO_SPLIT) {                                                       \
                aHi[ma][0] = __float_as_uint(x0) & 0xFFFFE000u;                   \
                aHi[ma][1] = __float_as_uint(x1) & 0xFFFFE000u;                   \
                aHi[ma][2] = __float_as_uint(x2) & 0xFFFFE000u;                   \
                aHi[ma][3] = __float_as_uint(x3) & 0xFFFFE000u;                   \
                aLo[ma][0] = __float_as_uint(x0 - __uint_as_float(aHi[ma][0]));   \
                aLo[ma][1] = __float_as_uint(x1 - __uint_as_float(aHi[ma][1]));   \
                aLo[ma][2] = __float_as_uint(x2 - __uint_as_float(aHi[ma][2]));   \
                aLo[ma][3] = __float_as_uint(x3 - __uint_as_float(aHi[ma][3]));   \
            } else {                                                              \
                aHi[ma][0] = f2tf32(x0); aHi[ma][1] = f2tf32(x1);                 \
                aHi[ma][2] = f2tf32(x2); aHi[ma][3] = f2tf32(x3);                 \
            }                                                                     \
        }                                                                         \
        _Pragma("unroll")                                                         \
        for (int na = 0; na < 8; na++) {                                          \
            int br = wn * 64 + na * 8 + g;                                        \
            uint32_t bb[2];                                                       \
            bb[0] = Bs[br * LDP + c0];                                            \
            bb[1] = Bs[br * LDP + c0 + 4];                                        \
            _Pragma("unroll")                                                     \
            for (int ma = 0; ma < 2; ma++) {                                      \
                mma_tf32(acc[ma][na], aHi[ma], bb);                               \
                if (DO_SPLIT) mma_tf32(acc[ma][na], aLo[ma], bb);                 \
            }                                                                     \
        }                                                                         \
    }                                                                             \
} while (0)

#define ACC_INIT()                                                                \
    float acc[2][8][4];                                                           \
    _Pragma("unroll")                                                             \
    for (int ma = 0; ma < 2; ma++)                                                \
        _Pragma("unroll")                                                         \
        for (int na = 0; na < 8; na++)                                            \
            _Pragma("unroll")                                                     \
            for (int q = 0; q < 4; q++) acc[ma][na][q] = 0.f

// ---------------- merged feature GEMM: Wh (y<2) / Whp (y>=2), split-A ----------
__global__ void __launch_bounds__(256, 2)
gemm_feat(const float* __restrict__ h_t, const float* __restrict__ h_prev,
          const float* __restrict__ pki, const float* __restrict__ pkc,
          const float* __restrict__ b_intra,
          const float* __restrict__ a_intra, const float* __restrict__ a_cross,
          float* __restrict__ Wh, float* __restrict__ Whp,
          float* __restrict__ es, float* __restrict__ ed, float* __restrict__ esP,
          int M) {
    extern __shared__ char smem[];
    uint32_t sb = smem_u32(smem);
    const int tid = threadIdx.x;
    const int wid = tid >> 5, lane = tid & 31;
    const int wm = wid & 3, wn = wid >> 2;
    const int g = lane >> 2, t = lane & 3;
    const int m0 = blockIdx.x * BMM;
    const int branch = blockIdx.y >> 1;           // 0: Wh, 1: Whp
    const int n0 = (blockIdx.y & 1) * 128;

    const float* A = branch ? h_prev : h_t;
    const float* B = branch ? pkc : pki;
    const float* avec = branch ? a_cross : a_intra;
    float* C = branch ? Whp : Wh;
    float* esT = branch ? esP : es;

    ACC_INIT();

    STAGE_CHUNK(A, B, 0, 0);
    for (int cc = 0; cc < 8; cc++) {
        int buf = cc & 1;
        if (cc < 7) { STAGE_CHUNK(A, B, (cc + 1) * 32, buf ^ 1); cp_wait<1>(); }
        else        cp_wait<0>();
        __syncthreads();
        COMPUTE_CHUNK(buf, 1);
        __syncthreads();
    }

    if (branch == 0) {
        #pragma unroll
        for (int na = 0; na < 8; na++)
            #pragma unroll
            for (int j = 0; j < 2; j++) {
                float bv = __ldg(&b_intra[n0 + wn * 64 + na * 8 + 2 * t + j]);
                acc[0][na][j]     += bv;
                acc[0][na][2 + j] += bv;
                acc[1][na][j]     += bv;
                acc[1][na][2 + j] += bv;
            }
    }

    int rbase = m0 + wm * 32;
    {
        int h = (blockIdx.y & 1) * 2 + wn;
        float e1[4] = {0.f, 0.f, 0.f, 0.f};
        float e2[4] = {0.f, 0.f, 0.f, 0.f};
        #pragma unroll
        for (int na = 0; na < 8; na++)
            #pragma unroll
            for (int j = 0; j < 2; j++) {
                int cw = na * 8 + 2 * t + j;
                float a1 = __ldg(&avec[h * 128 + cw]);
                float a2 = __ldg(&avec[h * 128 + 64 + cw]);
                e1[0] = fmaf(acc[0][na][j], a1, e1[0]);
                e1[1] = fmaf(acc[0][na][2 + j], a1, e1[1]);
                e1[2] = fmaf(acc[1][na][j], a1, e1[2]);
                e1[3] = fmaf(acc[1][na][2 + j], a1, e1[3]);
                e2[0] = fmaf(acc[0][na][j], a2, e2[0]);
                e2[1] = fmaf(acc[0][na][2 + j], a2, e2[1]);
                e2[2] = fmaf(acc[1][na][j], a2, e2[2]);
                e2[3] = fmaf(acc[1][na][2 + j], a2, e2[3]);
            }
        #pragma unroll
        for (int s = 0; s < 4; s++) {
            e1[s] += __shfl_xor_sync(0xffffffffu, e1[s], 1);
            e1[s] += __shfl_xor_sync(0xffffffffu, e1[s], 2);
            e2[s] += __shfl_xor_sync(0xffffffffu, e2[s], 1);
            e2[s] += __shfl_xor_sync(0xffffffffu, e2[s], 2);
        }
        if (t == 0) {
            int rows[4] = {rbase + g, rbase + 8 + g, rbase + 16 + g, rbase + 24 + g};
            #pragma unroll
            for (int s = 0; s < 4; s++) {
                if (rows[s] < M) {
                    esT[rows[s] * 4 + h] = e1[s];
                    if (branch == 0) ed[rows[s] * 4 + h] = e2[s];
                }
            }
        }
    }

    #pragma unroll
    for (int ma = 0; ma < 2; ma++) {
        int r0 = rbase + ma * 16 + g;
        #pragma unroll
        for (int na = 0; na < 8; na++) {
            int col = n0 + wn * 64 + na * 8 + 2 * t;
            if (r0 < M) {
                float2 v; v.x = acc[ma][na][0]; v.y = acc[ma][na][1];
                *(float2*)&C[(size_t)r0 * 256 + col] = v;
            }
            if (r0 + 8 < M) {
                float2 v; v.x = acc[ma][na][2]; v.y = acc[ma][na][3];
                *(float2*)&C[(size_t)(r0 + 8) * 256 + col] = v;
            }
        }
    }
}

// ---------------- merged gate GEMM ----------------
// y in [0,4): grz block y (K=512 concat) | y 4,5: gin | y 6,7: ghn
__global__ void __launch_bounds__(256, 2)
gemm_gates(const float* __restrict__ X, const float* __restrict__ H,
           const float* __restrict__ pih, const float* __restrict__ phh,
           const float* __restrict__ bih, const float* __restrict__ bhh,
           float* __restrict__ grz, float* __restrict__ gin, float* __restrict__ ghn,
           int M) {
    extern __shared__ char smem[];
    uint32_t sb = smem_u32(smem);
    const int tid = threadIdx.x;
    const int wid = tid >> 5, lane = tid & 31;
    const int wm = wid & 3, wn = wid >> 2;
    const int g = lane >> 2, t = lane & 3;
    const int m0 = blockIdx.x * BMM;
    const int by = blockIdx.y;
    const int mode = (by < 4) ? 0 : ((by < 6) ? 1 : 2);
    const int n0 = (mode == 0) ? by * 128 : (by & 1) * 128;

    const float* A1 = (mode == 2) ? H : X;
    const float* B1 = (mode == 0) ? pih : ((mode == 1) ? pih + 512 * 256 : phh + 512 * 256);
    const int nch = (mode == 0) ? 16 : 8;

    ACC_INIT();

    STAGE_CHUNK(A1, B1, 0, 0);
    for (int cc = 0; cc < nch; cc++) {
        int buf = cc & 1;
        if (cc < nch - 1) {
            int nc = cc + 1;
            const float* Ap = (mode == 0 && nc >= 8) ? H : A1;
            const float* Bp = (mode == 0 && nc >= 8) ? phh : B1;
            int koff = (nc & 7) * 32;
            STAGE_CHUNK(Ap, Bp, koff, buf ^ 1);
            cp_wait<1>();
        } else {
            cp_wait<0>();
        }
        __syncthreads();
        COMPUTE_CHUNK(buf, 0);
        __syncthreads();
    }

    int rbase = m0 + wm * 32;
    #pragma unroll
    for (int ma = 0; ma < 2; ma++) {
        int r0 = rbase + ma * 16 + g;
        #pragma unroll
        for (int na = 0; na < 8; na++) {
            int col = n0 + wn * 64 + na * 8 + 2 * t;
            float b0, b1;
            float* C; int ld; int ccol = col;
            if (mode == 0) {
                b0 = __ldg(&bih[col]) + __ldg(&bhh[col]);
                b1 = __ldg(&bih[col + 1]) + __ldg(&bhh[col + 1]);
                C = grz; ld = 512;
            } else if (mode == 1) {
                b0 = __ldg(&bih[512 + col]); b1 = __ldg(&bih[512 + col + 1]);
                C = gin; ld = 256;
            } else {
                b0 = __ldg(&bhh[512 + col]); b1 = __ldg(&bhh[512 + col + 1]);
                C = ghn; ld = 256;
            }
            if (r0 < M) {
                float2 v; v.x = acc[ma][na][0] + b0; v.y = acc[ma][na][1] + b1;
                *(float2*)&C[(size_t)r0 * ld + ccol] = v;
            }
            if (r0 + 8 < M) {
                float2 v; v.x = acc[ma][na][2] + b0; v.y = acc[ma][na][3] + b1;
                *(float2*)&C[(size_t)(r0 + 8) * ld + ccol] = v;
            }
        }
    }
}

// ---------------- merged packs ----------------
__global__ void pack_all(const float* __restrict__ Wi, const float* __restrict__ Wc,
                         const float* __restrict__ Wih, const float* __restrict__ Whh,
                         const float* __restrict__ ac,
                         float* __restrict__ pki, float* __restrict__ pkc,
                         float* __restrict__ pih, float* __restrict__ phh,
                         float* __restrict__ vmat) {
    int b = blockIdx.x;
    int tid = threadIdx.x;
    if (b < 256) {                       // pack_headwise intra
        int o = b * 256 + tid;
        int n = o >> 8, f = o & 255, h = n >> 6, dd = n & 63;
        pki[o] = __uint_as_float(f2tf32(Wi[(h * 256 + f) * 64 + dd]));
    } else if (b < 512) {                // pack_headwise cross
        int o = (b - 256) * 256 + tid;
        int n = o >> 8, f = o & 255, h = n >> 6, dd = n & 63;
        pkc[o] = __uint_as_float(f2tf32(Wc[(h * 256 + f) * 64 + dd]));
    } else if (b < 1280) {               // round W_ih
        int o = (b - 512) * 256 + tid;
        pih[o] = __uint_as_float(f2tf32(Wih[o]));
    } else if (b < 2048) {               // round W_hh
        int o = (b - 1280) * 256 + tid;
        phh[o] = __uint_as_float(f2tf32(Whh[o]));
    } else {                             // vmat (4 blocks)
        int o = (b - 2048) * 256 + tid;
        int f = o >> 2, h = o & 3;
        float s = 0.f;
        #pragma unroll 8
        for (int dd = 0; dd < 64; dd++)
            s = fmaf(Wc[(h * 256 + f) * 64 + dd], ac[h * 128 + 64 + dd], s);
        vmat[f * 4 + h] = s;
    }
}

// ---------------- intra-turn GAT aggregation + fused edX ----------------
__global__ __launch_bounds__(256)
void intra_agg(const float* __restrict__ Wh, const float* __restrict__ es,
               const float* __restrict__ ed, const float* __restrict__ ab,
               const int* __restrict__ src, const float* __restrict__ vmat,
               float* __restrict__ x, float* __restrict__ edX) {
    int d = blockIdx.x;
    int tid = threadIdx.x;
    int lane = tid & 31, wid = tid >> 5;
    __shared__ int   s_src[DEG_IN];
    __shared__ float se[NHEADS * DEG_IN];
    __shared__ float sred[8 * NHEADS];

    if (tid < DEG_IN) s_src[tid] = src[d * DEG_IN + tid];
    __syncthreads();

    if (tid < NHEADS * DEG_IN) {
        int i = tid & 15, h = tid >> 4;
        float e = es[s_src[i] * NHEADS + h] + ed[d * NHEADS + h] + ab[h];
        se[tid] = (e >= 0.f) ? e : ALPHA * e;
    }
    __syncthreads();

    if (tid < NHEADS) {
        float m = -1e30f;
        #pragma unroll
        for (int i = 0; i < DEG_IN; i++) m = fmaxf(m, se[tid * DEG_IN + i]);
        float s = 0.f;
        #pragma unroll
        for (int i = 0; i < DEG_IN; i++) {
            float ex = expf(se[tid * DEG_IN + i] - m);
            se[tid * DEG_IN + i] = ex;
            s += ex;
        }
        float inv = 1.f / fmaxf(s, 1e-9f);
        #pragma unroll
        for (int i = 0; i < DEG_IN; i++) se[tid * DEG_IN + i] *= inv;
    }
    __syncthreads();

    int h = tid >> 6;
    float acc = 0.f;
    #pragma unroll
    for (int i = 0; i < DEG_IN; i++)
        acc = fmaf(se[h * DEG_IN + i], Wh[s_src[i] * NHID + tid], acc);
    x[d * NHID + tid] = acc;

    float4 vm = *(const float4*)&vmat[tid * 4];
    float p0 = acc * vm.x, p1 = acc * vm.y, p2 = acc * vm.z, p3 = acc * vm.w;
    #pragma unroll
    for (int off = 16; off > 0; off >>= 1) {
        p0 += __shfl_xor_sync(0xffffffffu, p0, off);
        p1 += __shfl_xor_sync(0xffffffffu, p1, off);
        p2 += __shfl_xor_sync(0xffffffffu, p2, off);
        p3 += __shfl_xor_sync(0xffffffffu, p3, off);
    }
    if (lane == 0) {
        sred[wid * 4 + 0] = p0;
        sred[wid * 4 + 1] = p1;
        sred[wid * 4 + 2] = p2;
        sred[wid * 4 + 3] = p3;
    }
    __syncthreads();
    if (tid < NHEADS) {
        float s = 0.f;
        #pragma unroll
        for (int w = 0; w < 8; w++) s += sred[w * 4 + tid];
        edX[d * NHEADS + tid] = s;
    }
}

// ---------------- cross-turn GAT (counter + support fused) ----------------
__global__ __launch_bounds__(256)
void cross_agg(const float* __restrict__ Whp, const float* __restrict__ esP,
               const float* __restrict__ edX, const int* __restrict__ src_c,
               const int* __restrict__ src_s, float* __restrict__ hout) {
    int d = blockIdx.x;
    int tid = threadIdx.x;
    __shared__ int   sc[DEG_C], ss[DEG_C];
    __shared__ float se[2 * NHEADS * DEG_C];

    if (tid < DEG_C)           sc[tid]         = src_c[d * DEG_C + tid];
    else if (tid < 2 * DEG_C)  ss[tid - DEG_C] = src_s[d * DEG_C + (tid - DEG_C)];
    __syncthreads();

    if (tid < 64) {
        int which = tid >> 5;
        int tt = tid & 31;
        int i = tt & 7, h = tt >> 3;
        int s = which ? ss[i] : sc[i];
        float e = esP[s * NHEADS + h] + edX[d * NHEADS + h];
        se[tid] = (e >= 0.f) ? e : ALPHA * e;
    }
    __syncthreads();

    if (tid < 8) {
        float* ep = &se[(tid >> 2) * 32 + (tid & 3) * 8];
        float m = -1e30f;
        #pragma unroll
        for (int i = 0; i < DEG_C; i++) m = fmaxf(m, ep[i]);
        float s = 0.f;
        #pragma unroll
        for (int i = 0; i < DEG_C; i++) { float ex = expf(ep[i] - m); ep[i] = ex; s += ex; }
        float inv = 1.f / fmaxf(s, 1e-9f);
        #pragma unroll
        for (int i = 0; i < DEG_C; i++) ep[i] *= inv;
    }
    __syncthreads();

    int h = tid >> 6;
    float acc = 0.f;
    #pragma unroll
    for (int i = 0; i < DEG_C; i++)
        acc = fmaf(se[h * DEG_C + i], Whp[sc[i] * NHID + tid], acc);
    #pragma unroll
    for (int i = 0; i < DEG_C; i++)
        acc = fmaf(se[32 + h * DEG_C + i], Whp[ss[i] * NHID + tid], acc);
    hout[d * NHID + tid] = 0.5f * acc;
}

// ---------------- GRU elementwise (float4) ----------------
__global__ void gru_kernel(const float* __restrict__ grz, const float* __restrict__ gin,
                           const float* __restrict__ ghn, const float* __restrict__ h,
                           float* __restrict__ out) {
    int idx = blockIdx.x * 256 + threadIdx.x;         // float4 index; 64 per node
    int node = idx >> 6, c = idx & 63;
    float4 rr = *(const float4*)&grz[(size_t)node * 512 + c * 4];
    float4 zz = *(const float4*)&grz[(size_t)node * 512 + 256 + c * 4];
    float4 gn = *(const float4*)&gin[(size_t)idx * 4];
    float4 hn = *(const float4*)&ghn[(size_t)idx * 4];
    float4 hh = *(const float4*)&h[(size_t)idx * 4];
    float4 o;
    {
        float r = 1.f / (1.f + expf(-rr.x)), z = 1.f / (1.f + expf(-zz.x));
        o.x = (1.f - z) * tanhf(gn.x + r * hn.x) + z * hh.x;
    }
    {
        float r = 1.f / (1.f + expf(-rr.y)), z = 1.f / (1.f + expf(-zz.y));
        o.y = (1.f - z) * tanhf(gn.y + r * hn.y) + z * hh.y;
    }
    {
        float r = 1.f / (1.f + expf(-rr.z)), z = 1.f / (1.f + expf(-zz.z));
        o.z = (1.f - z) * tanhf(gn.z + r * hn.z) + z * hh.z;
    }
    {
        float r = 1.f / (1.f + expf(-rr.w)), z = 1.f / (1.f + expf(-zz.w));
        o.w = (1.f - z) * tanhf(gn.w + r * hn.w) + z * hh.w;
    }
    *(float4*)&out[(size_t)idx * 4] = o;
}

// ---------------- host launcher ----------------
extern "C" void kernel_launch(void* const* d_in, const int* in_sizes, int n_in,
                              void* d_out, int out_size) {
    const float* h_t      = (const float*)d_in[0];
    const float* h_prev   = (const float*)d_in[1];
    const float* W_intra  = (const float*)d_in[2];
    const float* b_intra  = (const float*)d_in[3];
    const float* a_intra  = (const float*)d_in[4];
    const float* ab_intra = (const float*)d_in[5];
    const float* W_cross  = (const float*)d_in[6];
    const float* a_cross  = (const float*)d_in[7];
    const float* W_ih     = (const float*)d_in[8];
    const float* W_hh     = (const float*)d_in[9];
    const float* b_ih     = (const float*)d_in[10];
    const float* b_hh     = (const float*)d_in[11];
    const int*   src_in   = (const int*)d_in[12];
    const int*   src_c    = (const int*)d_in[14];
    const int*   src_s    = (const int*)d_in[16];
    float* out = (float*)d_out;

    float *p_Wh, *p_x, *p_Whp, *p_h, *p_grz, *p_gin, *p_ghn;
    float *p_pki, *p_pkc, *p_pih, *p_phh, *p_vm, *p_es, *p_ed, *p_esP, *p_edX;
    cudaGetSymbolAddress((void**)&p_Wh,  d_Wh);
    cudaGetSymbolAddress((void**)&p_x,   d_x);
    cudaGetSymbolAddress((void**)&p_Whp, d_Whp);
    cudaGetSymbolAddress((void**)&p_h,   d_h);
    cudaGetSymbolAddress((void**)&p_grz, d_grz);
    cudaGetSymbolAddress((void**)&p_gin, d_gin);
    cudaGetSymbolAddress((void**)&p_ghn, d_ghn);
    cudaGetSymbolAddress((void**)&p_pki, d_pk_intra);
    cudaGetSymbolAddress((void**)&p_pkc, d_pk_cross);
    cudaGetSymbolAddress((void**)&p_pih, d_pih);
    cudaGetSymbolAddress((void**)&p_phh, d_phh);
    cudaGetSymbolAddress((void**)&p_vm,  d_vmat);
    cudaGetSymbolAddress((void**)&p_es,  d_es);
    cudaGetSymbolAddress((void**)&p_ed,  d_ed);
    cudaGetSymbolAddress((void**)&p_esP, d_esP);
    cudaGetSymbolAddress((void**)&p_edX, d_edX);

    cudaFuncSetAttribute(gemm_feat,  cudaFuncAttributeMaxDynamicSharedMemorySize, SMEMSZ);
    cudaFuncSetAttribute(gemm_gates, cudaFuncAttributeMaxDynamicSharedMemorySize, SMEMSZ);

    // 1. all packs in one launch
    pack_all<<<2052, 256>>>(W_intra, W_cross, W_ih, W_hh, a_cross,
                            p_pki, p_pkc, p_pih, p_phh, p_vm);

    // 2. Wh + Whp in one launch (split-A, fused dots)
    dim3 gF((NN + BMM - 1) / BMM, 4);
    gemm_feat<<<gF, 256, SMEMSZ>>>(h_t, h_prev, p_pki, p_pkc, b_intra,
                                   a_intra, a_cross, p_Wh, p_Whp,
                                   p_es, p_ed, p_esP, NN);
    // 3. intra GAT -> x (+ fused edX)
    intra_agg<<<NN, 256>>>(p_Wh, p_es, p_ed, ab_intra, src_in, p_vm, p_x, p_edX);
    // 4. cross GAT -> h
    cross_agg<<<NN, 256>>>(p_Whp, p_esP, p_edX, src_c, src_s, p_h);
    // 5. all gate GEMMs in one launch
    dim3 gG((NN + BMM - 1) / BMM, 8);
    gemm_gates<<<gG, 256, SMEMSZ>>>(p_x, p_h, p_pih, p_phh, b_ih, b_hh,
                                    p_grz, p_gin, p_ghn, NN);
    // 6. GRU elementwise -> out (float4)
    gru_kernel<<<NN / 4, 256>>>(p_grz, p_gin, p_ghn, p_h, out);
}

// round 9
// speedup vs baseline: 1.8129x; 1.1908x over previous
#include <cuda_runtime.h>
#include <cuda_bf16.h>
#include <math.h>
#include <stdint.h>

// ---------------- problem constants ----------------
#define NN      50000
#define NPREV   50000
#define NFEATS  256
#define NHID    256
#define NHEADS  4
#define HD      64
#define DEG_IN  16
#define DEG_C   8
#define ALPHA   0.2f

// ---------------- device scratch ----------------
__device__ float d_Wh  [NN * NHID];
__device__ float d_x   [NN * NHID];
__device__ float d_Whp [NPREV * NHID];
__device__ float d_h   [NN * NHID];
__device__ float d_grz [NN * 512];
__device__ float d_gin [NN * NHID];
__device__ float d_ghn [NN * NHID];
__device__ float d_pk_intra[NHID * NFEATS];
__device__ float d_pk_cross[NHID * NHID];
__device__ float d_pih[768 * 256];
__device__ float d_phh[768 * 256];
__device__ float d_vmat[NFEATS * NHEADS];
__device__ float d_es [NN * NHEADS];
__device__ float d_ed [NN * NHEADS];
__device__ float d_esP[NPREV * NHEADS];
__device__ float d_edX[NN * NHEADS];

// ---------------- helpers ----------------
__device__ __forceinline__ uint32_t smem_u32(const void* p) {
    uint32_t a;
    asm("{ .reg .u64 t; cvta.to.shared.u64 t, %1; cvt.u32.u64 %0, t; }" : "=r"(a) : "l"(p));
    return a;
}
__device__ __forceinline__ uint32_t f2tf32(float x) {
    uint32_t r;
    asm("cvt.rna.tf32.f32 %0, %1;" : "=r"(r) : "f"(x));
    return r;
}
__device__ __forceinline__ void cp16(uint32_t dst, const void* src) {
    asm volatile("cp.async.cg.shared.global [%0], [%1], 16;" :: "r"(dst), "l"(src));
}
__device__ __forceinline__ void cp_commit() {
    asm volatile("cp.async.commit_group;" ::: "memory");
}
template<int N>
__device__ __forceinline__ void cp_wait() {
    asm volatile("cp.async.wait_group %0;" :: "n"(N) : "memory");
}
__device__ __forceinline__ void mma_tf32(float* d, const uint32_t* a, const uint32_t* b) {
    asm volatile(
        "mma.sync.aligned.m16n8k8.row.col.f32.tf32.tf32.f32 "
        "{%0,%1,%2,%3},{%4,%5,%6,%7},{%8,%9},{%0,%1,%2,%3};"
        : "+f"(d[0]), "+f"(d[1]), "+f"(d[2]), "+f"(d[3])
        : "r"(a[0]), "r"(a[1]), "r"(a[2]), "r"(a[3]), "r"(b[0]), "r"(b[1]));
}

#define BMM 128
#define LDP 36
#define PLANE_B (128 * LDP * 4)
#define STAGE_B (2 * PLANE_B)
#define SMEMSZ  (2 * STAGE_B)

#define STAGE_CHUNK(Aptr, Bptr, koff, buf)                                        \
do {                                                                              \
    uint32_t abase = sb + (buf) * STAGE_B;                                        \
    uint32_t bbase = abase + PLANE_B;                                             \
    _Pragma("unroll")                                                             \
    for (int j = 0; j < 4; j++) {                                                 \
        int r = (tid >> 3) + j * 32;                                              \
        int row = m0 + r; if (row >= M) row = M - 1;                              \
        cp16(abase + r * (LDP * 4) + (tid & 7) * 16,                              \
             &(Aptr)[(size_t)row * 256 + (koff) + (tid & 7) * 4]);                \
    }                                                                             \
    _Pragma("unroll")                                                             \
    for (int j = 0; j < 4; j++) {                                                 \
        int r = (tid >> 3) + j * 32;                                              \
        cp16(bbase + r * (LDP * 4) + (tid & 7) * 16,                              \
             &(Bptr)[(size_t)(n0 + r) * 256 + (koff) + (tid & 7) * 4]);           \
    }                                                                             \
    cp_commit();                                                                  \
} while (0)

#define COMPUTE_CHUNK(buf, DO_SPLIT)                                              \
do {                                                                              \
    const float*    As = (const float*)(smem + (buf) * STAGE_B);                  \
    const uint32_t* Bs = (const uint32_t*)(smem + (buf) * STAGE_B + PLANE_B);     \
    _Pragma("unroll")                                                             \
    for (int ks = 0; ks < 4; ks++) {                                              \
        int c0 = ks * 8 + t;                                                      \
        uint32_t aHi[2][4], aLo[2][4];                                            \
        _Pragma("unroll")                                                         \
        for (int ma = 0; ma < 2; ma++) {                                          \
            int r0 = wm * 32 + ma * 16 + g;                                       \
            float x0 = As[r0 * LDP + c0];                                         \
            float x1 = As[(r0 + 8) * LDP + c0];                                   \
            float x2 = As[r0 * LDP + c0 + 4];                                     \
            float x3 = As[(r0 + 8) * LDP + c0 + 4];                               \
            if (DO_SPLIT) {                                                       \
                aHi[ma][0] = __float_as_uint(x0) & 0xFFFFE000u;                   \
                aHi[ma][1] = __float_as_uint(x1) & 0xFFFFE000u;                   \
                aHi[ma][2] = __float_as_uint(x2) & 0xFFFFE000u;                   \
                aHi[ma][3] = __float_as_uint(x3) & 0xFFFFE000u;                   \
                aLo[ma][0] = __float_as_uint(x0 - __uint_as_float(aHi[ma][0]));   \
                aLo[ma][1] = __float_as_uint(x1 - __uint_as_float(aHi[ma][1]));   \
                aLo[ma][2] = __float_as_uint(x2 - __uint_as_float(aHi[ma][2]));   \
                aLo[ma][3] = __float_as_uint(x3 - __uint_as_float(aHi[ma][3]));   \
            } else {                                                              \
                aHi[ma][0] = f2tf32(x0); aHi[ma][1] = f2tf32(x1);                 \
                aHi[ma][2] = f2tf32(x2); aHi[ma][3] = f2tf32(x3);                 \
            }                                                                     \
        }                                                                         \
        _Pragma("unroll")                                                         \
        for (int na = 0; na < 8; na++) {                                          \
            int br = wn * 64 + na * 8 + g;                                        \
            uint32_t bb[2];                                                       \
            bb[0] = Bs[br * LDP + c0];                                            \
            bb[1] = Bs[br * LDP + c0 + 4];                                        \
            _Pragma("unroll")                                                     \
            for (int ma = 0; ma < 2; ma++) {                                      \
                mma_tf32(acc[ma][na], aHi[ma], bb);                               \
                if (DO_SPLIT) mma_tf32(acc[ma][na], aLo[ma], bb);                 \
            }                                                                     \
        }                                                                         \
    }                                                                             \
} while (0)

#define ACC_INIT()                                                                \
    float acc[2][8][4];                                                           \
    _Pragma("unroll")                                                             \
    for (int ma = 0; ma < 2; ma++)                                                \
        _Pragma("unroll")                                                         \
        for (int na = 0; na < 8; na++)                                            \
            _Pragma("unroll")                                                     \
            for (int q = 0; q < 4; q++) acc[ma][na][q] = 0.f

// ---------------- merged feature GEMM: Wh (y<2) / Whp (y>=2), split-A ----------
__global__ void __launch_bounds__(256, 2)
gemm_feat(const float* __restrict__ h_t, const float* __restrict__ h_prev,
          const float* __restrict__ pki, const float* __restrict__ pkc,
          const float* __restrict__ b_intra,
          const float* __restrict__ a_intra, const float* __restrict__ a_cross,
          float* __restrict__ Wh, float* __restrict__ Whp,
          float* __restrict__ es, float* __restrict__ ed, float* __restrict__ esP,
          int M) {
    extern __shared__ char smem[];
    uint32_t sb = smem_u32(smem);
    const int tid = threadIdx.x;
    const int wid = tid >> 5, lane = tid & 31;
    const int wm = wid & 3, wn = wid >> 2;
    const int g = lane >> 2, t = lane & 3;
    const int m0 = blockIdx.x * BMM;
    const int branch = blockIdx.y >> 1;
    const int n0 = (blockIdx.y & 1) * 128;

    const float* A = branch ? h_prev : h_t;
    const float* B = branch ? pkc : pki;
    const float* avec = branch ? a_cross : a_intra;
    float* C = branch ? Whp : Wh;
    float* esT = branch ? esP : es;

    ACC_INIT();

    STAGE_CHUNK(A, B, 0, 0);
    for (int cc = 0; cc < 8; cc++) {
        int buf = cc & 1;
        if (cc < 7) { STAGE_CHUNK(A, B, (cc + 1) * 32, buf ^ 1); cp_wait<1>(); }
        else        cp_wait<0>();
        __syncthreads();
        COMPUTE_CHUNK(buf, 1);
        __syncthreads();
    }

    if (branch == 0) {
        #pragma unroll
        for (int na = 0; na < 8; na++)
            #pragma unroll
            for (int j = 0; j < 2; j++) {
                float bv = __ldg(&b_intra[n0 + wn * 64 + na * 8 + 2 * t + j]);
                acc[0][na][j]     += bv;
                acc[0][na][2 + j] += bv;
                acc[1][na][j]     += bv;
                acc[1][na][2 + j] += bv;
            }
    }

    int rbase = m0 + wm * 32;
    {
        int h = (blockIdx.y & 1) * 2 + wn;
        float e1[4] = {0.f, 0.f, 0.f, 0.f};
        float e2[4] = {0.f, 0.f, 0.f, 0.f};
        #pragma unroll
        for (int na = 0; na < 8; na++)
            #pragma unroll
            for (int j = 0; j < 2; j++) {
                int cw = na * 8 + 2 * t + j;
                float a1 = __ldg(&avec[h * 128 + cw]);
                float a2 = __ldg(&avec[h * 128 + 64 + cw]);
                e1[0] = fmaf(acc[0][na][j], a1, e1[0]);
                e1[1] = fmaf(acc[0][na][2 + j], a1, e1[1]);
                e1[2] = fmaf(acc[1][na][j], a1, e1[2]);
                e1[3] = fmaf(acc[1][na][2 + j], a1, e1[3]);
                e2[0] = fmaf(acc[0][na][j], a2, e2[0]);
                e2[1] = fmaf(acc[0][na][2 + j], a2, e2[1]);
                e2[2] = fmaf(acc[1][na][j], a2, e2[2]);
                e2[3] = fmaf(acc[1][na][2 + j], a2, e2[3]);
            }
        #pragma unroll
        for (int s = 0; s < 4; s++) {
            e1[s] += __shfl_xor_sync(0xffffffffu, e1[s], 1);
            e1[s] += __shfl_xor_sync(0xffffffffu, e1[s], 2);
            e2[s] += __shfl_xor_sync(0xffffffffu, e2[s], 1);
            e2[s] += __shfl_xor_sync(0xffffffffu, e2[s], 2);
        }
        if (t == 0) {
            int rows[4] = {rbase + g, rbase + 8 + g, rbase + 16 + g, rbase + 24 + g};
            #pragma unroll
            for (int s = 0; s < 4; s++) {
                if (rows[s] < M) {
                    esT[rows[s] * 4 + h] = e1[s];
                    if (branch == 0) ed[rows[s] * 4 + h] = e2[s];
                }
            }
        }
    }

    #pragma unroll
    for (int ma = 0; ma < 2; ma++) {
        int r0 = rbase + ma * 16 + g;
        #pragma unroll
        for (int na = 0; na < 8; na++) {
            int col = n0 + wn * 64 + na * 8 + 2 * t;
            if (r0 < M) {
                float2 v; v.x = acc[ma][na][0]; v.y = acc[ma][na][1];
                *(float2*)&C[(size_t)r0 * 256 + col] = v;
            }
            if (r0 + 8 < M) {
                float2 v; v.x = acc[ma][na][2]; v.y = acc[ma][na][3];
                *(float2*)&C[(size_t)(r0 + 8) * 256 + col] = v;
            }
        }
    }
}

// ---------------- merged gate GEMM ----------------
__global__ void __launch_bounds__(256, 2)
gemm_gates(const float* __restrict__ X, const float* __restrict__ H,
           const float* __restrict__ pih, const float* __restrict__ phh,
           const float* __restrict__ bih, const float* __restrict__ bhh,
           float* __restrict__ grz, float* __restrict__ gin, float* __restrict__ ghn,
           int M) {
    extern __shared__ char smem[];
    uint32_t sb = smem_u32(smem);
    const int tid = threadIdx.x;
    const int wid = tid >> 5, lane = tid & 31;
    const int wm = wid & 3, wn = wid >> 2;
    const int g = lane >> 2, t = lane & 3;
    const int m0 = blockIdx.x * BMM;
    const int by = blockIdx.y;
    const int mode = (by < 4) ? 0 : ((by < 6) ? 1 : 2);
    const int n0 = (mode == 0) ? by * 128 : (by & 1) * 128;

    const float* A1 = (mode == 2) ? H : X;
    const float* B1 = (mode == 0) ? pih : ((mode == 1) ? pih + 512 * 256 : phh + 512 * 256);
    const int nch = (mode == 0) ? 16 : 8;

    ACC_INIT();

    STAGE_CHUNK(A1, B1, 0, 0);
    for (int cc = 0; cc < nch; cc++) {
        int buf = cc & 1;
        if (cc < nch - 1) {
            int nc = cc + 1;
            const float* Ap = (mode == 0 && nc >= 8) ? H : A1;
            const float* Bp = (mode == 0 && nc >= 8) ? phh : B1;
            int koff = (nc & 7) * 32;
            STAGE_CHUNK(Ap, Bp, koff, buf ^ 1);
            cp_wait<1>();
        } else {
            cp_wait<0>();
        }
        __syncthreads();
        COMPUTE_CHUNK(buf, 0);
        __syncthreads();
    }

    int rbase = m0 + wm * 32;
    #pragma unroll
    for (int ma = 0; ma < 2; ma++) {
        int r0 = rbase + ma * 16 + g;
        #pragma unroll
        for (int na = 0; na < 8; na++) {
            int col = n0 + wn * 64 + na * 8 + 2 * t;
            float b0, b1;
            float* C; int ld;
            if (mode == 0) {
                b0 = __ldg(&bih[col]) + __ldg(&bhh[col]);
                b1 = __ldg(&bih[col + 1]) + __ldg(&bhh[col + 1]);
                C = grz; ld = 512;
            } else if (mode == 1) {
                b0 = __ldg(&bih[512 + col]); b1 = __ldg(&bih[512 + col + 1]);
                C = gin; ld = 256;
            } else {
                b0 = __ldg(&bhh[512 + col]); b1 = __ldg(&bhh[512 + col + 1]);
                C = ghn; ld = 256;
            }
            if (r0 < M) {
                float2 v; v.x = acc[ma][na][0] + b0; v.y = acc[ma][na][1] + b1;
                *(float2*)&C[(size_t)r0 * ld + col] = v;
            }
            if (r0 + 8 < M) {
                float2 v; v.x = acc[ma][na][2] + b0; v.y = acc[ma][na][3] + b1;
                *(float2*)&C[(size_t)(r0 + 8) * ld + col] = v;
            }
        }
    }
}

// ---------------- merged packs ----------------
__global__ void pack_all(const float* __restrict__ Wi, const float* __restrict__ Wc,
                         const float* __restrict__ Wih, const float* __restrict__ Whh,
                         const float* __restrict__ ac,
                         float* __restrict__ pki, float* __restrict__ pkc,
                         float* __restrict__ pih, float* __restrict__ phh,
                         float* __restrict__ vmat) {
    int b = blockIdx.x;
    int tid = threadIdx.x;
    if (b < 256) {
        int o = b * 256 + tid;
        int n = o >> 8, f = o & 255, h = n >> 6, dd = n & 63;
        pki[o] = __uint_as_float(f2tf32(Wi[(h * 256 + f) * 64 + dd]));
    } else if (b < 512) {
        int o = (b - 256) * 256 + tid;
        int n = o >> 8, f = o & 255, h = n >> 6, dd = n & 63;
        pkc[o] = __uint_as_float(f2tf32(Wc[(h * 256 + f) * 64 + dd]));
    } else if (b < 1280) {
        int o = (b - 512) * 256 + tid;
        pih[o] = __uint_as_float(f2tf32(Wih[o]));
    } else if (b < 2048) {
        int o = (b - 1280) * 256 + tid;
        phh[o] = __uint_as_float(f2tf32(Whh[o]));
    } else {
        int o = (b - 2048) * 256 + tid;
        int f = o >> 2, h = o & 3;
        float s = 0.f;
        #pragma unroll 8
        for (int dd = 0; dd < 64; dd++)
            s = fmaf(Wc[(h * 256 + f) * 64 + dd], ac[h * 128 + 64 + dd], s);
        vmat[f * 4 + h] = s;
    }
}

// ---------------- intra-turn GAT: 4 nodes/block, float4 cols, fused edX --------
__global__ __launch_bounds__(256)
void intra_agg(const float* __restrict__ Wh, const float* __restrict__ es,
               const float* __restrict__ ed, const float* __restrict__ ab,
               const int* __restrict__ src, const float* __restrict__ vmat,
               float* __restrict__ x, float* __restrict__ edX) {
    const int tid = threadIdx.x;
    const int d0 = blockIdx.x * 4;
    const int sub = tid >> 6;         // node in block
    const int c4 = tid & 63;          // float4 column
    __shared__ int   ssrc[4][DEG_IN];
    __shared__ float se[4][NHEADS * DEG_IN];     // [sub][h*16+i]
    __shared__ float sred[4][2][NHEADS];

    if (tid < 64)
        ssrc[tid >> 4][tid & 15] = src[(d0 + (tid >> 4)) * DEG_IN + (tid & 15)];
    __syncthreads();

    {   // all 256 threads: one logit each
        int s2 = tid >> 6;
        int r = tid & 63;
        int h = r >> 4, i = r & 15;
        float e = es[ssrc[s2][i] * 4 + h] + ed[(d0 + s2) * 4 + h] + ab[h];
        se[s2][r] = (e >= 0.f) ? e : ALPHA * e;
    }
    __syncthreads();

    if (tid < 16) {   // 16 softmaxes of width 16
        int s2 = tid >> 2, h = tid & 3;
        float* ep = &se[s2][h * 16];
        float m = -1e30f;
        #pragma unroll
        for (int i = 0; i < DEG_IN; i++) m = fmaxf(m, ep[i]);
        float s = 0.f;
        #pragma unroll
        for (int i = 0; i < DEG_IN; i++) { float ex = expf(ep[i] - m); ep[i] = ex; s += ex; }
        float inv = 1.f / fmaxf(s, 1e-9f);
        #pragma unroll
        for (int i = 0; i < DEG_IN; i++) ep[i] *= inv;
    }
    __syncthreads();

    const int dd = d0 + sub;
    const int h = c4 >> 4;
    float4 acc = make_float4(0.f, 0.f, 0.f, 0.f);
    #pragma unroll
    for (int i = 0; i < DEG_IN; i++) {
        float w = se[sub][h * 16 + i];
        float4 v = *(const float4*)&Wh[(size_t)ssrc[sub][i] * 256 + c4 * 4];
        acc.x = fmaf(w, v.x, acc.x);
        acc.y = fmaf(w, v.y, acc.y);
        acc.z = fmaf(w, v.z, acc.z);
        acc.w = fmaf(w, v.w, acc.w);
    }
    *(float4*)&x[(size_t)dd * 256 + c4 * 4] = acc;

    // edX: p[h'] = sum_f acc_f * vmat[f][h'], f = c4*4+q
    float4 vm0 = *(const float4*)&vmat[(c4 * 4 + 0) * 4];
    float4 vm1 = *(const float4*)&vmat[(c4 * 4 + 1) * 4];
    float4 vm2 = *(const float4*)&vmat[(c4 * 4 + 2) * 4];
    float4 vm3 = *(const float4*)&vmat[(c4 * 4 + 3) * 4];
    float p[4];
    p[0] = acc.x * vm0.x + acc.y * vm1.x + acc.z * vm2.x + acc.w * vm3.x;
    p[1] = acc.x * vm0.y + acc.y * vm1.y + acc.z * vm2.y + acc.w * vm3.y;
    p[2] = acc.x * vm0.z + acc.y * vm1.z + acc.z * vm2.z + acc.w * vm3.z;
    p[3] = acc.x * vm0.w + acc.y * vm1.w + acc.z * vm2.w + acc.w * vm3.w;
    #pragma unroll
    for (int off = 16; off > 0; off >>= 1) {
        p[0] += __shfl_xor_sync(0xffffffffu, p[0], off);
        p[1] += __shfl_xor_sync(0xffffffffu, p[1], off);
        p[2] += __shfl_xor_sync(0xffffffffu, p[2], off);
        p[3] += __shfl_xor_sync(0xffffffffu, p[3], off);
    }
    if ((tid & 31) == 0) {
        int wp = (c4 >> 5);      // which warp-half of this node
        sred[sub][wp][0] = p[0];
        sred[sub][wp][1] = p[1];
        sred[sub][wp][2] = p[2];
        sred[sub][wp][3] = p[3];
    }
    __syncthreads();
    if (tid < 16) {
        int s2 = tid >> 2, hh = tid & 3;
        edX[(d0 + s2) * 4 + hh] = sred[s2][0][hh] + sred[s2][1][hh];
    }
}

// ---------------- cross-turn GAT: 4 nodes/block, float4 cols ----------------
__global__ __launch_bounds__(256)
void cross_agg(const float* __restrict__ Whp, const float* __restrict__ esP,
               const float* __restrict__ edX, const int* __restrict__ src_c,
               const int* __restrict__ src_s, float* __restrict__ hout) {
    const int tid = threadIdx.x;
    const int d0 = blockIdx.x * 4;
    const int sub = tid >> 6;
    const int c4 = tid & 63;
    __shared__ int   ssrc[4][16];            // [sub][0-7 counter, 8-15 support]
    __shared__ float se[4][64];              // [sub][which*32 + h*8 + i]

    if (tid < 64) {
        int s2 = tid >> 4, i = tid & 15;
        int dd = d0 + s2;
        ssrc[s2][i] = (i < 8) ? src_c[dd * 8 + i] : src_s[dd * 8 + (i - 8)];
    }
    __syncthreads();

    {   // 256 logits, one per thread
        int s2 = tid >> 6;
        int r = tid & 63;
        int which = r >> 5;
        int h = (r >> 3) & 3;
        int i = r & 7;
        int s = ssrc[s2][which * 8 + i];
        float e = esP[s * 4 + h] + edX[(d0 + s2) * 4 + h];
        se[s2][r] = (e >= 0.f) ? e : ALPHA * e;
    }
    __syncthreads();

    if (tid < 32) {   // 32 softmaxes of width 8
        int s2 = tid >> 3, grp = tid & 7;
        float* ep = &se[s2][(grp >> 2) * 32 + (grp & 3) * 8];
        float m = -1e30f;
        #pragma unroll
        for (int i = 0; i < DEG_C; i++) m = fmaxf(m, ep[i]);
        float s = 0.f;
        #pragma unroll
        for (int i = 0; i < DEG_C; i++) { float ex = expf(ep[i] - m); ep[i] = ex; s += ex; }
        float inv = 1.f / fmaxf(s, 1e-9f);
        #pragma unroll
        for (int i = 0; i < DEG_C; i++) ep[i] *= inv;
    }
    __syncthreads();

    const int dd = d0 + sub;
    const int h = c4 >> 4;
    float4 acc = make_float4(0.f, 0.f, 0.f, 0.f);
    #pragma unroll
    for (int i = 0; i < DEG_C; i++) {
        float w = se[sub][h * 8 + i];
        float4 v = *(const float4*)&Whp[(size_t)ssrc[sub][i] * 256 + c4 * 4];
        acc.x = fmaf(w, v.x, acc.x);
        acc.y = fmaf(w, v.y, acc.y);
        acc.z = fmaf(w, v.z, acc.z);
        acc.w = fmaf(w, v.w, acc.w);
    }
    #pragma unroll
    for (int i = 0; i < DEG_C; i++) {
        float w = se[sub][32 + h * 8 + i];
        float4 v = *(const float4*)&Whp[(size_t)ssrc[sub][8 + i] * 256 + c4 * 4];
        acc.x = fmaf(w, v.x, acc.x);
        acc.y = fmaf(w, v.y, acc.y);
        acc.z = fmaf(w, v.z, acc.z);
        acc.w = fmaf(w, v.w, acc.w);
    }
    float4 o;
    o.x = 0.5f * acc.x; o.y = 0.5f * acc.y; o.z = 0.5f * acc.z; o.w = 0.5f * acc.w;
    *(float4*)&hout[(size_t)dd * 256 + c4 * 4] = o;
}

// ---------------- GRU elementwise (float4) ----------------
__global__ void gru_kernel(const float* __restrict__ grz, const float* __restrict__ gin,
                           const float* __restrict__ ghn, const float* __restrict__ h,
                           float* __restrict__ out) {
    int idx = blockIdx.x * 256 + threadIdx.x;
    int node = idx >> 6, c = idx & 63;
    float4 rr = *(const float4*)&grz[(size_t)node * 512 + c * 4];
    float4 zz = *(const float4*)&grz[(size_t)node * 512 + 256 + c * 4];
    float4 gn = *(const float4*)&gin[(size_t)idx * 4];
    float4 hn = *(const float4*)&ghn[(size_t)idx * 4];
    float4 hh = *(const float4*)&h[(size_t)idx * 4];
    float4 o;
    { float r = 1.f/(1.f+expf(-rr.x)), z = 1.f/(1.f+expf(-zz.x));
      o.x = (1.f-z)*tanhf(gn.x + r*hn.x) + z*hh.x; }
    { float r = 1.f/(1.f+expf(-rr.y)), z = 1.f/(1.f+expf(-zz.y));
      o.y = (1.f-z)*tanhf(gn.y + r*hn.y) + z*hh.y; }
    { float r = 1.f/(1.f+expf(-rr.z)), z = 1.f/(1.f+expf(-zz.z));
      o.z = (1.f-z)*tanhf(gn.z + r*hn.z) + z*hh.z; }
    { float r = 1.f/(1.f+expf(-rr.w)), z = 1.f/(1.f+expf(-zz.w));
      o.w = (1.f-z)*tanhf(gn.w + r*hn.w) + z*hh.w; }
    *(float4*)&out[(size_t)idx * 4] = o;
}

// ---------------- host launcher ----------------
extern "C" void kernel_launch(void* const* d_in, const int* in_sizes, int n_in,
                              void* d_out, int out_size) {
    const float* h_t      = (const float*)d_in[0];
    const float* h_prev   = (const float*)d_in[1];
    const float* W_intra  = (const float*)d_in[2];
    const float* b_intra  = (const float*)d_in[3];
    const float* a_intra  = (const float*)d_in[4];
    const float* ab_intra = (const float*)d_in[5];
    const float* W_cross  = (const float*)d_in[6];
    const float* a_cross  = (const float*)d_in[7];
    const float* W_ih     = (const float*)d_in[8];
    const float* W_hh     = (const float*)d_in[9];
    const float* b_ih     = (const float*)d_in[10];
    const float* b_hh     = (const float*)d_in[11];
    const int*   src_in   = (const int*)d_in[12];
    const int*   src_c    = (const int*)d_in[14];
    const int*   src_s    = (const int*)d_in[16];
    float* out = (float*)d_out;

    float *p_Wh, *p_x, *p_Whp, *p_h, *p_grz, *p_gin, *p_ghn;
    float *p_pki, *p_pkc, *p_pih, *p_phh, *p_vm, *p_es, *p_ed, *p_esP, *p_edX;
    cudaGetSymbolAddress((void**)&p_Wh,  d_Wh);
    cudaGetSymbolAddress((void**)&p_x,   d_x);
    cudaGetSymbolAddress((void**)&p_Whp, d_Whp);
    cudaGetSymbolAddress((void**)&p_h,   d_h);
    cudaGetSymbolAddress((void**)&p_grz, d_grz);
    cudaGetSymbolAddress((void**)&p_gin, d_gin);
    cudaGetSymbolAddress((void**)&p_ghn, d_ghn);
    cudaGetSymbolAddress((void**)&p_pki, d_pk_intra);
    cudaGetSymbolAddress((void**)&p_pkc, d_pk_cross);
    cudaGetSymbolAddress((void**)&p_pih, d_pih);
    cudaGetSymbolAddress((void**)&p_phh, d_phh);
    cudaGetSymbolAddress((void**)&p_vm,  d_vmat);
    cudaGetSymbolAddress((void**)&p_es,  d_es);
    cudaGetSymbolAddress((void**)&p_ed,  d_ed);
    cudaGetSymbolAddress((void**)&p_esP, d_esP);
    cudaGetSymbolAddress((void**)&p_edX, d_edX);

    cudaFuncSetAttribute(gemm_feat,  cudaFuncAttributeMaxDynamicSharedMemorySize, SMEMSZ);
    cudaFuncSetAttribute(gemm_gates, cudaFuncAttributeMaxDynamicSharedMemorySize, SMEMSZ);

    pack_all<<<2052, 256>>>(W_intra, W_cross, W_ih, W_hh, a_cross,
                            p_pki, p_pkc, p_pih, p_phh, p_vm);

    dim3 gF((NN + BMM - 1) / BMM, 4);
    gemm_feat<<<gF, 256, SMEMSZ>>>(h_t, h_prev, p_pki, p_pkc, b_intra,
                                   a_intra, a_cross, p_Wh, p_Whp,
                                   p_es, p_ed, p_esP, NN);
    intra_agg<<<NN / 4, 256>>>(p_Wh, p_es, p_ed, ab_intra, src_in, p_vm, p_x, p_edX);
    cross_agg<<<NN / 4, 256>>>(p_Whp, p_esP, p_edX, src_c, src_s, p_h);
    dim3 gG((NN + BMM - 1) / BMM, 8);
    gemm_gates<<<gG, 256, SMEMSZ>>>(p_x, p_h, p_pih, p_phh, b_ih, b_hh,
                                    p_grz, p_gin, p_ghn, NN);
    gru_kernel<<<NN / 4, 256>>>(p_grz, p_gin, p_ghn, p_h, out);
}

// round 11
// speedup vs baseline: 1.8633x; 1.0278x over previous
#include <cuda_runtime.h>
#include <cuda_bf16.h>
#include <math.h>
#include <stdint.h>

// ---------------- problem constants ----------------
#define NN      50000
#define NPREV   50000
#define NFEATS  256
#define NHID    256
#define NHEADS  4
#define HD      64
#define DEG_IN  16
#define DEG_C   8
#define ALPHA   0.2f

// ---------------- device scratch ----------------
__device__ float d_Wh  [NN * NHID];
__device__ float d_x   [NN * NHID];          // tf32-rounded (only gates read it)
__device__ float d_Whp [NPREV * NHID];
__device__ float d_h   [NN * NHID];          // full precision (gru)
__device__ float d_hr  [NN * NHID];          // tf32-rounded (gates)
__device__ float d_grz [NN * 512];
__device__ float d_gin [NN * NHID];
__device__ float d_ghn [NN * NHID];
__device__ float d_pk_intra[NHID * NFEATS];  // tf32-rounded, K pair-interleaved
__device__ float d_pk_cross[NHID * NHID];
__device__ float d_pih[768 * 256];
__device__ float d_phh[768 * 256];
__device__ float d_vmat[NFEATS * NHEADS];
__device__ float d_es [NN * NHEADS];
__device__ float d_ed [NN * NHEADS];
__device__ float d_esP[NPREV * NHEADS];
__device__ float d_edX[NN * NHEADS];

// ---------------- helpers ----------------
__device__ __forceinline__ uint32_t smem_u32(const void* p) {
    uint32_t a;
    asm("{ .reg .u64 t; cvta.to.shared.u64 t, %1; cvt.u32.u64 %0, t; }" : "=r"(a) : "l"(p));
    return a;
}
__device__ __forceinline__ uint32_t f2tf32(float x) {
    uint32_t r;
    asm("cvt.rna.tf32.f32 %0, %1;" : "=r"(r) : "f"(x));
    return r;
}
__device__ __forceinline__ void cp16(uint32_t dst, const void* src) {
    asm volatile("cp.async.cg.shared.global [%0], [%1], 16;" :: "r"(dst), "l"(src));
}
__device__ __forceinline__ void cp_commit() {
    asm volatile("cp.async.commit_group;" ::: "memory");
}
template<int N>
__device__ __forceinline__ void cp_wait() {
    asm volatile("cp.async.wait_group %0;" :: "n"(N) : "memory");
}
__device__ __forceinline__ void mma_tf32(float* d, const uint32_t* a, const uint32_t* b) {
    asm volatile(
        "mma.sync.aligned.m16n8k8.row.col.f32.tf32.tf32.f32 "
        "{%0,%1,%2,%3},{%4,%5,%6,%7},{%8,%9},{%0,%1,%2,%3};"
        : "+f"(d[0]), "+f"(d[1]), "+f"(d[2]), "+f"(d[3])
        : "r"(a[0]), "r"(a[1]), "r"(a[2]), "r"(a[3]), "r"(b[0]), "r"(b[1]));
}

#define BMM 128
#define LDPA 36
#define LDPB 40
#define PLANE_A  (128 * LDPA * 4)    // 18432
#define PLANE_BB (128 * LDPB * 4)    // 20480
#define STAGE_SZ (PLANE_A + PLANE_BB)
#define SMEMSZ   (2 * STAGE_SZ)      // 77824

#define STAGE_CHUNK(Aptr, Bptr, koff, buf)                                        \
do {                                                                              \
    uint32_t abase = sb + (buf) * STAGE_SZ;                                       \
    uint32_t bbase = abase + PLANE_A;                                             \
    _Pragma("unroll")                                                             \
    for (int j = 0; j < 4; j++) {                                                 \
        int r = (tid >> 3) + j * 32;                                              \
        int row = m0 + r; if (row >= M) row = M - 1;                              \
        cp16(abase + r * (LDPA * 4) + (tid & 7) * 16,                             \
             &(Aptr)[(size_t)row * 256 + (koff) + (tid & 7) * 4]);                \
    }                                                                             \
    _Pragma("unroll")                                                             \
    for (int j = 0; j < 4; j++) {                                                 \
        int r = (tid >> 3) + j * 32;                                              \
        cp16(bbase + r * (LDPB * 4) + (tid & 7) * 16,                             \
             &(Bptr)[(size_t)(n0 + r) * 256 + (koff) + (tid & 7) * 4]);           \
    }                                                                             \
    cp_commit();                                                                  \
} while (0)

// DO_SPLIT: 1 = mask-split A (fp32-accurate), 0 = A already tf32 (raw loads)
#define COMPUTE_CHUNK(buf, DO_SPLIT)                                              \
do {                                                                              \
    const float*    As = (const float*)(smem + (buf) * STAGE_SZ);                 \
    const uint32_t* Au = (const uint32_t*)As;                                     \
    const uint32_t* Bs = (const uint32_t*)(smem + (buf) * STAGE_SZ + PLANE_A);    \
    _Pragma("unroll")                                                             \
    for (int ks = 0; ks < 4; ks++) {                                              \
        int c0 = ks * 8 + t;                                                      \
        uint32_t aHi[2][4], aLo[2][4];                                            \
        _Pragma("unroll")                                                         \
        for (int ma = 0; ma < 2; ma++) {                                          \
            int r0 = wm * 32 + ma * 16 + g;                                       \
            if (DO_SPLIT) {                                                       \
                float x0 = As[r0 * LDPA + c0];                                    \
                float x1 = As[(r0 + 8) * LDPA + c0];                              \
                float x2 = As[r0 * LDPA + c0 + 4];                                \
                float x3 = As[(r0 + 8) * LDPA + c0 + 4];                          \
                aHi[ma][0] = __float_as_uint(x0) & 0xFFFFE000u;                   \
                aHi[ma][1] = __float_as_uint(x1) & 0xFFFFE000u;                   \
                aHi[ma][2] = __float_as_uint(x2) & 0xFFFFE000u;                   \
                aHi[ma][3] = __float_as_uint(x3) & 0xFFFFE000u;                   \
                aLo[ma][0] = __float_as_uint(x0 - __uint_as_float(aHi[ma][0]));   \
                aLo[ma][1] = __float_as_uint(x1 - __uint_as_float(aHi[ma][1]));   \
                aLo[ma][2] = __float_as_uint(x2 - __uint_as_float(aHi[ma][2]));   \
                aLo[ma][3] = __float_as_uint(x3 - __uint_as_float(aHi[ma][3]));   \
            } else {                                                              \
                aHi[ma][0] = Au[r0 * LDPA + c0];                                  \
                aHi[ma][1] = Au[(r0 + 8) * LDPA + c0];                            \
                aHi[ma][2] = Au[r0 * LDPA + c0 + 4];                              \
                aHi[ma][3] = Au[(r0 + 8) * LDPA + c0 + 4];                        \
            }                                                                     \
        }                                                                         \
        _Pragma("unroll")                                                         \
        for (int na = 0; na < 8; na++) {                                          \
            int br = wn * 64 + na * 8 + g;                                        \
            uint2 bb2 = *(const uint2*)&Bs[br * LDPB + ks * 8 + 2 * t];           \
            _Pragma("unroll")                                                     \
            for (int ma = 0; ma < 2; ma++) {                                      \
                mma_tf32(acc[ma][na], aHi[ma], &bb2.x);                           \
                if (DO_SPLIT) mma_tf32(acc[ma][na], aLo[ma], &bb2.x);             \
            }                                                                     \
        }                                                                         \
    }                                                                             \
} while (0)

#define ACC_INIT()                                                                \
    float acc[2][8][4];                                                           \
    _Pragma("unroll")                                                             \
    for (int ma = 0; ma < 2; ma++)                                                \
        _Pragma("unroll")                                                         \
        for (int na = 0; na < 8; na++)                                            \
            _Pragma("unroll")                                                     \
            for (int q = 0; q < 4; q++) acc[ma][na][q] = 0.f

// ---------------- merged feature GEMM: Wh (y<2) / Whp (y>=2), split-A ----------
__global__ void __launch_bounds__(256, 2)
gemm_feat(const float* __restrict__ h_t, const float* __restrict__ h_prev,
          const float* __restrict__ pki, const float* __restrict__ pkc,
          const float* __restrict__ b_intra,
          const float* __restrict__ a_intra, const float* __restrict__ a_cross,
          float* __restrict__ Wh, float* __restrict__ Whp,
          float* __restrict__ es, float* __restrict__ ed, float* __restrict__ esP,
          int M) {
    extern __shared__ char smem[];
    uint32_t sb = smem_u32(smem);
    const int tid = threadIdx.x;
    const int wid = tid >> 5, lane = tid & 31;
    const int wm = wid & 3, wn = wid >> 2;
    const int g = lane >> 2, t = lane & 3;
    const int m0 = blockIdx.x * BMM;
    const int branch = blockIdx.y >> 1;
    const int n0 = (blockIdx.y & 1) * 128;

    const float* A = branch ? h_prev : h_t;
    const float* B = branch ? pkc : pki;
    const float* avec = branch ? a_cross : a_intra;
    float* C = branch ? Whp : Wh;
    float* esT = branch ? esP : es;

    ACC_INIT();

    STAGE_CHUNK(A, B, 0, 0);
    for (int cc = 0; cc < 8; cc++) {
        int buf = cc & 1;
        if (cc < 7) { STAGE_CHUNK(A, B, (cc + 1) * 32, buf ^ 1); cp_wait<1>(); }
        else        cp_wait<0>();
        __syncthreads();
        COMPUTE_CHUNK(buf, 1);
        __syncthreads();
    }

    if (branch == 0) {
        #pragma unroll
        for (int na = 0; na < 8; na++)
            #pragma unroll
            for (int j = 0; j < 2; j++) {
                float bv = __ldg(&b_intra[n0 + wn * 64 + na * 8 + 2 * t + j]);
                acc[0][na][j]     += bv;
                acc[0][na][2 + j] += bv;
                acc[1][na][j]     += bv;
                acc[1][na][2 + j] += bv;
            }
    }

    int rbase = m0 + wm * 32;
    {
        int h = (blockIdx.y & 1) * 2 + wn;
        float e1[4] = {0.f, 0.f, 0.f, 0.f};
        float e2[4] = {0.f, 0.f, 0.f, 0.f};
        #pragma unroll
        for (int na = 0; na < 8; na++)
            #pragma unroll
            for (int j = 0; j < 2; j++) {
                int cw = na * 8 + 2 * t + j;
                float a1 = __ldg(&avec[h * 128 + cw]);
                float a2 = __ldg(&avec[h * 128 + 64 + cw]);
                e1[0] = fmaf(acc[0][na][j], a1, e1[0]);
                e1[1] = fmaf(acc[0][na][2 + j], a1, e1[1]);
                e1[2] = fmaf(acc[1][na][j], a1, e1[2]);
                e1[3] = fmaf(acc[1][na][2 + j], a1, e1[3]);
                e2[0] = fmaf(acc[0][na][j], a2, e2[0]);
                e2[1] = fmaf(acc[0][na][2 + j], a2, e2[1]);
                e2[2] = fmaf(acc[1][na][j], a2, e2[2]);
                e2[3] = fmaf(acc[1][na][2 + j], a2, e2[3]);
            }
        #pragma unroll
        for (int s = 0; s < 4; s++) {
            e1[s] += __shfl_xor_sync(0xffffffffu, e1[s], 1);
            e1[s] += __shfl_xor_sync(0xffffffffu, e1[s], 2);
            e2[s] += __shfl_xor_sync(0xffffffffu, e2[s], 1);
            e2[s] += __shfl_xor_sync(0xffffffffu, e2[s], 2);
        }
        if (t == 0) {
            int rows[4] = {rbase + g, rbase + 8 + g, rbase + 16 + g, rbase + 24 + g};
            #pragma unroll
            for (int s = 0; s < 4; s++) {
                if (rows[s] < M) {
                    esT[rows[s] * 4 + h] = e1[s];
                    if (branch == 0) ed[rows[s] * 4 + h] = e2[s];
                }
            }
        }
    }

    #pragma unroll
    for (int ma = 0; ma < 2; ma++) {
        int r0 = rbase + ma * 16 + g;
        #pragma unroll
        for (int na = 0; na < 8; na++) {
            int col = n0 + wn * 64 + na * 8 + 2 * t;
            if (r0 < M) {
                float2 v; v.x = acc[ma][na][0]; v.y = acc[ma][na][1];
                *(float2*)&C[(size_t)r0 * 256 + col] = v;
            }
            if (r0 + 8 < M) {
                float2 v; v.x = acc[ma][na][2]; v.y = acc[ma][na][3];
                *(float2*)&C[(size_t)(r0 + 8) * 256 + col] = v;
            }
        }
    }
}

// ---------------- merged gate GEMM (A = pre-rounded xr/hr, no in-loop cvt) ----
__global__ void __launch_bounds__(256, 2)
gemm_gates(const float* __restrict__ X, const float* __restrict__ Hr,
           const float* __restrict__ pih, const float* __restrict__ phh,
           const float* __restrict__ bih, const float* __restrict__ bhh,
           float* __restrict__ grz, float* __restrict__ gin, float* __restrict__ ghn,
           int M) {
    extern __shared__ char smem[];
    uint32_t sb = smem_u32(smem);
    const int tid = threadIdx.x;
    const int wid = tid >> 5, lane = tid & 31;
    const int wm = wid & 3, wn = wid >> 2;
    const int g = lane >> 2, t = lane & 3;
    const int m0 = blockIdx.x * BMM;
    const int by = blockIdx.y;
    const int mode = (by < 4) ? 0 : ((by < 6) ? 1 : 2);
    const int n0 = (mode == 0) ? by * 128 : (by & 1) * 128;

    const float* A1 = (mode == 2) ? Hr : X;
    const float* B1 = (mode == 0) ? pih : ((mode == 1) ? pih + 512 * 256 : phh + 512 * 256);
    const int nch = (mode == 0) ? 16 : 8;

    ACC_INIT();

    STAGE_CHUNK(A1, B1, 0, 0);
    for (int cc = 0; cc < nch; cc++) {
        int buf = cc & 1;
        if (cc < nch - 1) {
            int nc = cc + 1;
            const float* Ap = (mode == 0 && nc >= 8) ? Hr : A1;
            const float* Bp = (mode == 0 && nc >= 8) ? phh : B1;
            int koff = (nc & 7) * 32;
            STAGE_CHUNK(Ap, Bp, koff, buf ^ 1);
            cp_wait<1>();
        } else {
            cp_wait<0>();
        }
        __syncthreads();
        COMPUTE_CHUNK(buf, 0);
        __syncthreads();
    }

    int rbase = m0 + wm * 32;
    #pragma unroll
    for (int ma = 0; ma < 2; ma++) {
        int r0 = rbase + ma * 16 + g;
        #pragma unroll
        for (int na = 0; na < 8; na++) {
            int col = n0 + wn * 64 + na * 8 + 2 * t;
            float b0, b1;
            float* C; int ld;
            if (mode == 0) {
                b0 = __ldg(&bih[col]) + __ldg(&bhh[col]);
                b1 = __ldg(&bih[col + 1]) + __ldg(&bhh[col + 1]);
                C = grz; ld = 512;
            } else if (mode == 1) {
                b0 = __ldg(&bih[512 + col]); b1 = __ldg(&bih[512 + col + 1]);
                C = gin; ld = 256;
            } else {
                b0 = __ldg(&bhh[512 + col]); b1 = __ldg(&bhh[512 + col + 1]);
                C = ghn; ld = 256;
            }
            if (r0 < M) {
                float2 v; v.x = acc[ma][na][0] + b0; v.y = acc[ma][na][1] + b1;
                *(float2*)&C[(size_t)r0 * ld + col] = v;
            }
            if (r0 + 8 < M) {
                float2 v; v.x = acc[ma][na][2] + b0; v.y = acc[ma][na][3] + b1;
                *(float2*)&C[(size_t)(r0 + 8) * ld + col] = v;
            }
        }
    }
}

// ---------------- merged packs (tf32-round + K pair-interleave) ----------------
// physical kp within each 8-group holds logical klog: kp=2u   -> klog = u
//                                                     kp=2u+1 -> klog = u+4
__global__ void pack_all(const float* __restrict__ Wi, const float* __restrict__ Wc,
                         const float* __restrict__ Wih, const float* __restrict__ Whh,
                         const float* __restrict__ ac,
                         float* __restrict__ pki, float* __restrict__ pkc,
                         float* __restrict__ pih, float* __restrict__ phh,
                         float* __restrict__ vmat) {
    int b = blockIdx.x;
    int tid = threadIdx.x;
    if (b < 512) {
        int o = (b & 255) * 256 + tid;
        int n = o >> 8, kp = o & 255;
        int f = (kp & 0xF8) | ((kp >> 1) & 3) | ((kp & 1) << 2);
        int h = n >> 6, dd = n & 63;
        const float* W = (b < 256) ? Wi : Wc;
        float* out = (b < 256) ? pki : pkc;
        out[o] = __uint_as_float(f2tf32(W[(h * 256 + f) * 64 + dd]));
    } else if (b < 2048) {
        int blk = (b < 1280) ? (b - 512) : (b - 1280);      // FIXED: proper offset
        int o = blk * 256 + tid;
        int n = o >> 8, kp = o & 255;
        int k = (kp & 0xF8) | ((kp >> 1) & 3) | ((kp & 1) << 2);
        const float* W = (b < 1280) ? Wih : Whh;
        float* out = (b < 1280) ? pih : phh;
        out[o] = __uint_as_float(f2tf32(W[n * 256 + k]));
    } else {
        int o = (b - 2048) * 256 + tid;
        int f = o >> 2, h = o & 3;
        float s = 0.f;
        #pragma unroll 8
        for (int dd = 0; dd < 64; dd++)
            s = fmaf(Wc[(h * 256 + f) * 64 + dd], ac[h * 128 + 64 + dd], s);
        vmat[f * 4 + h] = s;
    }
}

// ---------------- intra-turn GAT: 4 nodes/block, float4, rounded-x store ------
__global__ __launch_bounds__(256)
void intra_agg(const float* __restrict__ Wh, const float* __restrict__ es,
               const float* __restrict__ ed, const float* __restrict__ ab,
               const int* __restrict__ src, const float* __restrict__ vmat,
               float* __restrict__ x, float* __restrict__ edX) {
    const int tid = threadIdx.x;
    const int d0 = blockIdx.x * 4;
    const int sub = tid >> 6;
    const int c4 = tid & 63;
    __shared__ int   ssrc[4][DEG_IN];
    __shared__ float se[4][NHEADS * DEG_IN];
    __shared__ float sred[4][2][NHEADS];

    if (tid < 64)
        ssrc[tid >> 4][tid & 15] = src[(d0 + (tid >> 4)) * DEG_IN + (tid & 15)];
    __syncthreads();

    {
        int s2 = tid >> 6;
        int r = tid & 63;
        int h = r >> 4, i = r & 15;
        float e = es[ssrc[s2][i] * 4 + h] + ed[(d0 + s2) * 4 + h] + ab[h];
        se[s2][r] = (e >= 0.f) ? e : ALPHA * e;
    }
    __syncthreads();

    if (tid < 16) {
        int s2 = tid >> 2, h = tid & 3;
        float* ep = &se[s2][h * 16];
        float m = -1e30f;
        #pragma unroll
        for (int i = 0; i < DEG_IN; i++) m = fmaxf(m, ep[i]);
        float s = 0.f;
        #pragma unroll
        for (int i = 0; i < DEG_IN; i++) { float ex = expf(ep[i] - m); ep[i] = ex; s += ex; }
        float inv = 1.f / fmaxf(s, 1e-9f);
        #pragma unroll
        for (int i = 0; i < DEG_IN; i++) ep[i] *= inv;
    }
    __syncthreads();

    const int dd = d0 + sub;
    const int h = c4 >> 4;
    float4 acc = make_float4(0.f, 0.f, 0.f, 0.f);
    #pragma unroll
    for (int i = 0; i < DEG_IN; i++) {
        float w = se[sub][h * 16 + i];
        float4 v = *(const float4*)&Wh[(size_t)ssrc[sub][i] * 256 + c4 * 4];
        acc.x = fmaf(w, v.x, acc.x);
        acc.y = fmaf(w, v.y, acc.y);
        acc.z = fmaf(w, v.z, acc.z);
        acc.w = fmaf(w, v.w, acc.w);
    }
    float4 xr;
    xr.x = __uint_as_float(f2tf32(acc.x));
    xr.y = __uint_as_float(f2tf32(acc.y));
    xr.z = __uint_as_float(f2tf32(acc.z));
    xr.w = __uint_as_float(f2tf32(acc.w));
    *(float4*)&x[(size_t)dd * 256 + c4 * 4] = xr;

    float4 vm0 = *(const float4*)&vmat[(c4 * 4 + 0) * 4];
    float4 vm1 = *(const float4*)&vmat[(c4 * 4 + 1) * 4];
    float4 vm2 = *(const float4*)&vmat[(c4 * 4 + 2) * 4];
    float4 vm3 = *(const float4*)&vmat[(c4 * 4 + 3) * 4];
    float p[4];
    p[0] = acc.x * vm0.x + acc.y * vm1.x + acc.z * vm2.x + acc.w * vm3.x;
    p[1] = acc.x * vm0.y + acc.y * vm1.y + acc.z * vm2.y + acc.w * vm3.y;
    p[2] = acc.x * vm0.z + acc.y * vm1.z + acc.z * vm2.z + acc.w * vm3.z;
    p[3] = acc.x * vm0.w + acc.y * vm1.w + acc.z * vm2.w + acc.w * vm3.w;
    #pragma unroll
    for (int off = 16; off > 0; off >>= 1) {
        p[0] += __shfl_xor_sync(0xffffffffu, p[0], off);
        p[1] += __shfl_xor_sync(0xffffffffu, p[1], off);
        p[2] += __shfl_xor_sync(0xffffffffu, p[2], off);
        p[3] += __shfl_xor_sync(0xffffffffu, p[3], off);
    }
    if ((tid & 31) == 0) {
        int wp = (c4 >> 5);
        sred[sub][wp][0] = p[0];
        sred[sub][wp][1] = p[1];
        sred[sub][wp][2] = p[2];
        sred[sub][wp][3] = p[3];
    }
    __syncthreads();
    if (tid < 16) {
        int s2 = tid >> 2, hh = tid & 3;
        edX[(d0 + s2) * 4 + hh] = sred[s2][0][hh] + sred[s2][1][hh];
    }
}

// ---------------- cross-turn GAT: 4 nodes/block, dual h store ----------------
__global__ __launch_bounds__(256)
void cross_agg(const float* __restrict__ Whp, const float* __restrict__ esP,
               const float* __restrict__ edX, const int* __restrict__ src_c,
               const int* __restrict__ src_s, float* __restrict__ hout,
               float* __restrict__ hr) {
    const int tid = threadIdx.x;
    const int d0 = blockIdx.x * 4;
    const int sub = tid >> 6;
    const int c4 = tid & 63;
    __shared__ int   ssrc[4][16];
    __shared__ float se[4][64];

    if (tid < 64) {
        int s2 = tid >> 4, i = tid & 15;
        int dd = d0 + s2;
        ssrc[s2][i] = (i < 8) ? src_c[dd * 8 + i] : src_s[dd * 8 + (i - 8)];
    }
    __syncthreads();

    {
        int s2 = tid >> 6;
        int r = tid & 63;
        int which = r >> 5;
        int h = (r >> 3) & 3;
        int i = r & 7;
        int s = ssrc[s2][which * 8 + i];
        float e = esP[s * 4 + h] + edX[(d0 + s2) * 4 + h];
        se[s2][r] = (e >= 0.f) ? e : ALPHA * e;
    }
    __syncthreads();

    if (tid < 32) {
        int s2 = tid >> 3, grp = tid & 7;
        float* ep = &se[s2][(grp >> 2) * 32 + (grp & 3) * 8];
        float m = -1e30f;
        #pragma unroll
        for (int i = 0; i < DEG_C; i++) m = fmaxf(m, ep[i]);
        float s = 0.f;
        #pragma unroll
        for (int i = 0; i < DEG_C; i++) { float ex = expf(ep[i] - m); ep[i] = ex; s += ex; }
        float inv = 1.f / fmaxf(s, 1e-9f);
        #pragma unroll
        for (int i = 0; i < DEG_C; i++) ep[i] *= inv;
    }
    __syncthreads();

    const int dd = d0 + sub;
    const int h = c4 >> 4;
    float4 acc = make_float4(0.f, 0.f, 0.f, 0.f);
    #pragma unroll
    for (int i = 0; i < DEG_C; i++) {
        float w = se[sub][h * 8 + i];
        float4 v = *(const float4*)&Whp[(size_t)ssrc[sub][i] * 256 + c4 * 4];
        acc.x = fmaf(w, v.x, acc.x);
        acc.y = fmaf(w, v.y, acc.y);
        acc.z = fmaf(w, v.z, acc.z);
        acc.w = fmaf(w, v.w, acc.w);
    }
    #pragma unroll
    for (int i = 0; i < DEG_C; i++) {
        float w = se[sub][32 + h * 8 + i];
        float4 v = *(const float4*)&Whp[(size_t)ssrc[sub][8 + i] * 256 + c4 * 4];
        acc.x = fmaf(w, v.x, acc.x);
        acc.y = fmaf(w, v.y, acc.y);
        acc.z = fmaf(w, v.z, acc.z);
        acc.w = fmaf(w, v.w, acc.w);
    }
    float4 o;
    o.x = 0.5f * acc.x; o.y = 0.5f * acc.y; o.z = 0.5f * acc.z; o.w = 0.5f * acc.w;
    *(float4*)&hout[(size_t)dd * 256 + c4 * 4] = o;
    float4 orr;
    orr.x = __uint_as_float(f2tf32(o.x));
    orr.y = __uint_as_float(f2tf32(o.y));
    orr.z = __uint_as_float(f2tf32(o.z));
    orr.w = __uint_as_float(f2tf32(o.w));
    *(float4*)&hr[(size_t)dd * 256 + c4 * 4] = orr;
}

// ---------------- GRU elementwise (float4) ----------------
__global__ void gru_kernel(const float* __restrict__ grz, const float* __restrict__ gin,
                           const float* __restrict__ ghn, const float* __restrict__ h,
                           float* __restrict__ out) {
    int idx = blockIdx.x * 256 + threadIdx.x;
    int node = idx >> 6, c = idx & 63;
    float4 rr = *(const float4*)&grz[(size_t)node * 512 + c * 4];
    float4 zz = *(const float4*)&grz[(size_t)node * 512 + 256 + c * 4];
    float4 gn = *(const float4*)&gin[(size_t)idx * 4];
    float4 hn = *(const float4*)&ghn[(size_t)idx * 4];
    float4 hh = *(const float4*)&h[(size_t)idx * 4];
    float4 o;
    { float r = 1.f/(1.f+expf(-rr.x)), z = 1.f/(1.f+expf(-zz.x));
      o.x = (1.f-z)*tanhf(gn.x + r*hn.x) + z*hh.x; }
    { float r = 1.f/(1.f+expf(-rr.y)), z = 1.f/(1.f+expf(-zz.y));
      o.y = (1.f-z)*tanhf(gn.y + r*hn.y) + z*hh.y; }
    { float r = 1.f/(1.f+expf(-rr.z)), z = 1.f/(1.f+expf(-zz.z));
      o.z = (1.f-z)*tanhf(gn.z + r*hn.z) + z*hh.z; }
    { float r = 1.f/(1.f+expf(-rr.w)), z = 1.f/(1.f+expf(-zz.w));
      o.w = (1.f-z)*tanhf(gn.w + r*hn.w) + z*hh.w; }
    *(float4*)&out[(size_t)idx * 4] = o;
}

// ---------------- host launcher ----------------
extern "C" void kernel_launch(void* const* d_in, const int* in_sizes, int n_in,
                              void* d_out, int out_size) {
    const float* h_t      = (const float*)d_in[0];
    const float* h_prev   = (const float*)d_in[1];
    const float* W_intra  = (const float*)d_in[2];
    const float* b_intra  = (const float*)d_in[3];
    const float* a_intra  = (const float*)d_in[4];
    const float* ab_intra = (const float*)d_in[5];
    const float* W_cross  = (const float*)d_in[6];
    const float* a_cross  = (const float*)d_in[7];
    const float* W_ih     = (const float*)d_in[8];
    const float* W_hh     = (const float*)d_in[9];
    const float* b_ih     = (const float*)d_in[10];
    const float* b_hh     = (const float*)d_in[11];
    const int*   src_in   = (const int*)d_in[12];
    const int*   src_c    = (const int*)d_in[14];
    const int*   src_s    = (const int*)d_in[16];
    float* out = (float*)d_out;

    float *p_Wh, *p_x, *p_Whp, *p_h, *p_hr, *p_grz, *p_gin, *p_ghn;
    float *p_pki, *p_pkc, *p_pih, *p_phh, *p_vm, *p_es, *p_ed, *p_esP, *p_edX;
    cudaGetSymbolAddress((void**)&p_Wh,  d_Wh);
    cudaGetSymbolAddress((void**)&p_x,   d_x);
    cudaGetSymbolAddress((void**)&p_Whp, d_Whp);
    cudaGetSymbolAddress((void**)&p_h,   d_h);
    cudaGetSymbolAddress((void**)&p_hr,  d_hr);
    cudaGetSymbolAddress((void**)&p_grz, d_grz);
    cudaGetSymbolAddress((void**)&p_gin, d_gin);
    cudaGetSymbolAddress((void**)&p_ghn, d_ghn);
    cudaGetSymbolAddress((void**)&p_pki, d_pk_intra);
    cudaGetSymbolAddress((void**)&p_pkc, d_pk_cross);
    cudaGetSymbolAddress((void**)&p_pih, d_pih);
    cudaGetSymbolAddress((void**)&p_phh, d_phh);
    cudaGetSymbolAddress((void**)&p_vm,  d_vmat);
    cudaGetSymbolAddress((void**)&p_es,  d_es);
    cudaGetSymbolAddress((void**)&p_ed,  d_ed);
    cudaGetSymbolAddress((void**)&p_esP, d_esP);
    cudaGetSymbolAddress((void**)&p_edX, d_edX);

    cudaFuncSetAttribute(gemm_feat,  cudaFuncAttributeMaxDynamicSharedMemorySize, SMEMSZ);
    cudaFuncSetAttribute(gemm_gates, cudaFuncAttributeMaxDynamicSharedMemorySize, SMEMSZ);

    pack_all<<<2052, 256>>>(W_intra, W_cross, W_ih, W_hh, a_cross,
                            p_pki, p_pkc, p_pih, p_phh, p_vm);

    dim3 gF((NN + BMM - 1) / BMM, 4);
    gemm_feat<<<gF, 256, SMEMSZ>>>(h_t, h_prev, p_pki, p_pkc, b_intra,
                                   a_intra, a_cross, p_Wh, p_Whp,
                                   p_es, p_ed, p_esP, NN);
    intra_agg<<<NN / 4, 256>>>(p_Wh, p_es, p_ed, ab_intra, src_in, p_vm, p_x, p_edX);
    cross_agg<<<NN / 4, 256>>>(p_Whp, p_esP, p_edX, src_c, src_s, p_h, p_hr);
    dim3 gG((NN + BMM - 1) / BMM, 8);
    gemm_gates<<<gG, 256, SMEMSZ>>>(p_x, p_hr, p_pih, p_phh, b_ih, b_hh,
                                    p_grz, p_gin, p_ghn, NN);
    gru_kernel<<<NN / 4, 256>>>(p_grz, p_gin, p_ghn, p_h, out);
}